// round 6
// baseline (speedup 1.0000x reference)
#include <cuda_runtime.h>

typedef unsigned long long u64;

#define HH 224
#define WW 224
#define IMG (HH * WW)
#define NPASS 9
#define W3MASK 0xFFFFFFFFull

// bits 0..k-1 of word j (j*64 .. j*64+63) of a 224-bit mask
__device__ __forceinline__ u64 mask_lt(int k, int j) {
    int lo = j * 64;
    if (k <= lo) return 0ull;
    if (k >= lo + 64) return ~0ull;
    return (1ull << (k - lo)) - 1ull;
}

__global__ __launch_bounds__(128) void mask_ca_kernel(const float* __restrict__ x,
                                                      float* __restrict__ out) {
    __shared__ u64 s_mask[HH][4];   // current mask (post rect-fill)
    __shared__ u64 s_b1[HH][4];     // base == exactly one of below/right
    __shared__ u64 s_b2[HH][4];     // base == both
    __shared__ u64 s_n[HH][4];      // serial-scan output (pre rect-fill)
    __shared__ int s_flags[HH];     // bit0: g(r-1)==g(r)==g(r+1); bit1: (b1|b2)==0
    __shared__ u64 s_cmA[4];        // column-OR of s_n (atomic)
    __shared__ int s_hminA, s_hmaxA;
    __shared__ int s_chg2[2];       // change flag, double-buffered by pass parity

    const int tid  = threadIdx.x;
    const int lane = tid & 31;
    const int warp = tid >> 5;
    const float* xi = x + (size_t)blockIdx.x * IMG;
    float* oi = out + (size_t)blockIdx.x * IMG;

    // ---- pack input: threshold > 0.8 into 224-bit rows (4x u64) ----
    for (int r = warp; r < HH; r += 4) {
        const float* row = xi + r * WW;
        unsigned b[7];
#pragma unroll
        for (int c = 0; c < 7; c++)
            b[c] = __ballot_sync(0xFFFFFFFFu, row[c * 32 + lane] > 0.8f);
        if (lane == 0) {
            s_mask[r][0] = (u64)b[0] | ((u64)b[1] << 32);
            s_mask[r][1] = (u64)b[2] | ((u64)b[3] << 32);
            s_mask[r][2] = (u64)b[4] | ((u64)b[5] << 32);
            s_mask[r][3] = (u64)b[6];
        }
    }
    if (tid == 0) {
        s_cmA[0] = s_cmA[1] = s_cmA[2] = s_cmA[3] = 0ull;
        s_hminA = 1 << 30; s_hmaxA = -1;
        s_chg2[0] = 0; s_chg2[1] = 0;
    }
    __syncthreads();

    // ---- initial b1/b2 + flags from packed input ----
    for (int r = tid; r < HH; r += 128) {
        u64 g0 = s_mask[r][0], g1 = s_mask[r][1], g2 = s_mask[r][2], g3 = s_mask[r][3];
        u64 n0, n1, n2, n3;
        if (r < HH - 2) {
            n0 = s_mask[r + 1][0]; n1 = s_mask[r + 1][1];
            n2 = s_mask[r + 1][2]; n3 = s_mask[r + 1][3];
        } else if (r == HH - 2) {
            n0 = ~0ull; n1 = ~0ull; n2 = ~0ull; n3 = W3MASK;   // below(H-2)=gt
        } else {
            n0 = n1 = n2 = n3 = 0ull;                           // below(H-1)=0
        }
        u64 bl0 = g0 & n0, bl1 = g1 & n1, bl2 = g2 & n2, bl3 = g3 & n3;
        u64 rt0 = ((g0 >> 1) | (g1 << 63)) & g0;
        u64 rt1 = ((g1 >> 1) | (g2 << 63)) & g1;
        u64 rt2 = ((g2 >> 1) | (g3 << 63)) & g2;
        u64 rt3 = ((g3 >> 1) | (1ull << 30)) & g3;   // right(W-2)=gt, right(W-1)=0
        s_b1[r][0] = bl0 ^ rt0; s_b1[r][1] = bl1 ^ rt1;
        s_b1[r][2] = bl2 ^ rt2; s_b1[r][3] = bl3 ^ rt3;
        s_b2[r][0] = bl0 & rt0; s_b2[r][1] = bl1 & rt1;
        s_b2[r][2] = bl2 & rt2; s_b2[r][3] = bl3 & rt3;
        int fl = (((bl0 | rt0) | (bl1 | rt1) | (bl2 | rt2) | (bl3 | rt3)) == 0ull) ? 2 : 0;
        if (r >= 1 && r <= HH - 3) {
            u64 m0 = s_mask[r - 1][0], m1 = s_mask[r - 1][1];
            u64 m2 = s_mask[r - 1][2], m3 = s_mask[r - 1][3];
            u64 d = (m0 ^ g0) | (m1 ^ g1) | (m2 ^ g2) | (m3 ^ g3)
                  | (g0 ^ n0) | (g1 ^ n1) | (g2 ^ n2) | (g3 ^ n3);
            fl |= (d == 0ull) ? 1 : 0;
        }
        s_flags[r] = fl;
    }
    __syncthreads();

    for (int pass = 0; pass < NPASS; pass++) {
        // ---- serial raster recurrence (thread 0) ----
        if (tid == 0) {
            s_chg2[(pass + 1) & 1] = 0;   // pre-clear NEXT pass's flag (no reader until then)
            u64 p10 = ~0ull, p11 = ~0ull, p12 = ~0ull, p13 = W3MASK;  // virtual row -1 = ones
            u64 p20 = 0, p21 = 0, p22 = 0, p23 = 0;                   // virtual row -2 = zeros
            int e1 = 0, e2 = 0;   // nn(r-1)==nn(r-2), nn(r-2)==nn(r-3)
            int p1z = 0;          // nn(r-1) == 0
            for (int r = 0; r < HH; r++) {
                const int fl = s_flags[r];
                if (fl & 2) {
                    // zero row: b1|b2==0 -> nn=0 for ANY ab (fill cannot seed:
                    // O=0 so carry masks stay empty and F stays 0)
                    s_n[r][0] = 0ull; s_n[r][1] = 0ull; s_n[r][2] = 0ull; s_n[r][3] = 0ull;
                    e2 = e1; e1 = p1z; p1z = 1;
                    p20 = p10; p21 = p11; p22 = p12; p23 = p13;
                    p10 = 0ull; p11 = 0ull; p12 = 0ull; p13 = 0ull;
                    continue;
                }
                if (e1 & e2 & fl) {
                    // hit: b(r)==b(r-1) and ab(r)==ab(r-1) => nn(r)==nn(r-1)==p1
                    s_n[r][0] = p10; s_n[r][1] = p11; s_n[r][2] = p12; s_n[r][3] = p13;
                    p20 = p10; p21 = p11; p22 = p12; p23 = p13;   // p1 unchanged
                    e2 = e1; e1 = 1;                              // p1z unchanged
                    continue;
                }
                u64 ab0 = p10 & p20, ab1 = p11 & p21, ab2 = p12 & p22, ab3 = p13 & p23;
                u64 b10 = s_b1[r][0], b11 = s_b1[r][1], b12 = s_b1[r][2], b13 = s_b1[r][3];
                u64 b20 = s_b2[r][0], b21 = s_b2[r][1], b22 = s_b2[r][2], b23 = s_b2[r][3];
                // a = base + above; O: a>=2, P: a==1
                u64 O0 = b20 | (b10 & ab0), O1 = b21 | (b11 & ab1);
                u64 O2 = b22 | (b12 & ab2), O3 = b23 | (b13 & ab3);
                u64 P0 = (b10 ^ ab0) & ~b20, P1 = (b11 ^ ab1) & ~b21;
                u64 P2 = (b12 ^ ab2) & ~b22, P3 = (b13 ^ ab3) & ~b23;
                u64 F0 = 0, F1 = 0, F2 = 0, F3 = 0;
                if (P0 | P1 | P2 | P3) {
                    // run starts: S = P & ~(P<<1)   (virtual P(-1)=0)
                    u64 S0 = P0 & ~(P0 << 1);
                    u64 S1 = P1 & ~((P1 << 1) | (P0 >> 63));
                    u64 S2 = P2 & ~((P2 << 1) | (P1 >> 63));
                    u64 S3 = P3 & ~((P3 << 1) | (P2 >> 63));
                    // seed: runs whose carry-in n(s-1)&n(s-2)==1 under k=O
                    // virtual n(-1)=1, n(-2)=0
                    u64 gs0 = S0 & ((O0 << 1) | 1ull) & ((O0 << 2) | 2ull);
                    u64 gs1 = S1 & ((O1 << 1) | (O0 >> 63)) & ((O1 << 2) | (O0 >> 62));
                    u64 gs2 = S2 & ((O2 << 1) | (O1 >> 63)) & ((O2 << 2) | (O1 >> 62));
                    u64 gs3 = S3 & ((O3 << 1) | (O2 >> 63)) & ((O3 << 2) | (O2 >> 62));
                    if (gs0 | gs1 | gs2 | gs3) {
                        // gs monotone; F is a pure function of gs -> iterate on gs
                        for (int it = 0; it < 256; it++) {
                            // 224-bit add: sum = P + gs (ripple flips seeded runs to 0)
                            u64 s0 = P0 + gs0; u64 cy = (s0 < P0);
                            u64 u1 = P1 + cy; u64 cA = (u1 < P1);
                            u64 s1 = u1 + gs1; cy = cA | (s1 < u1);
                            u64 u2 = P2 + cy; cA = (u2 < P2);
                            u64 s2 = u2 + gs2; cy = cA | (s2 < u2);
                            u64 s3 = P3 + gs3 + cy;
                            F0 = P0 & ~s0; F1 = P1 & ~s1; F2 = P2 & ~s2; F3 = P3 & ~s3;
                            u64 k0 = O0 | F0, k1 = O1 | F1, k2 = O2 | F2, k3 = O3 | F3;
                            u64 gn0 = S0 & ((k0 << 1) | 1ull) & ((k0 << 2) | 2ull);
                            u64 gn1 = S1 & ((k1 << 1) | (k0 >> 63)) & ((k1 << 2) | (k0 >> 62));
                            u64 gn2 = S2 & ((k2 << 1) | (k1 >> 63)) & ((k2 << 2) | (k1 >> 62));
                            u64 gn3 = S3 & ((k3 << 1) | (k2 >> 63)) & ((k3 << 2) | (k2 >> 62));
                            u64 ch = (gn0 ^ gs0) | (gn1 ^ gs1) | (gn2 ^ gs2) | (gn3 ^ gs3);
                            if (!ch) break;
                            gs0 = gn0; gs1 = gn1; gs2 = gn2; gs3 = gn3;
                        }
                    }
                }
                u64 nn0 = O0 | F0, nn1 = O1 | F1, nn2 = O2 | F2, nn3 = O3 | F3;
                s_n[r][0] = nn0; s_n[r][1] = nn1; s_n[r][2] = nn2; s_n[r][3] = nn3;
                u64 de = (nn0 ^ p10) | (nn1 ^ p11) | (nn2 ^ p12) | (nn3 ^ p13);
                e2 = e1; e1 = (de == 0ull);
                p1z = ((nn0 | nn1 | nn2 | nn3) == 0ull);
                p20 = p10; p21 = p11; p22 = p12; p23 = p13;
                p10 = nn0; p11 = nn1; p12 = nn2; p13 = nn3;
            }
        }
        __syncthreads();   // B1: s_n ready

        // ---- phase A: bbox reduction over s_n via shared atomics ----
        {
            int r0 = tid, r1 = tid + 128;
            u64 a0 = s_n[r0][0], a1 = s_n[r0][1], a2 = s_n[r0][2], a3 = s_n[r0][3];
            u64 c0 = 0, c1 = 0, c2 = 0, c3 = 0;
            bool nzA = (a0 | a1 | a2 | a3) != 0ull;
            bool nzB = false;
            if (r1 < HH) {
                c0 = s_n[r1][0]; c1 = s_n[r1][1]; c2 = s_n[r1][2]; c3 = s_n[r1][3];
                nzB = (c0 | c1 | c2 | c3) != 0ull;
            }
            if (nzA | nzB) {
                atomicOr(&s_cmA[0], a0 | c0);
                atomicOr(&s_cmA[1], a1 | c1);
                atomicOr(&s_cmA[2], a2 | c2);
                atomicOr(&s_cmA[3], a3 | c3);
                atomicMin(&s_hminA, nzA ? r0 : r1);
                atomicMax(&s_hmaxA, nzB ? r1 : r0);
            }
        }
        __syncthreads();   // B2: bbox final

        // ---- phase B: all threads compute rect locally; apply + diff + next b/flags ----
        {
            int hmin = s_hminA, hmax = s_hmaxA;
            u64 cm0 = s_cmA[0], cm1 = s_cmA[1], cm2 = s_cmA[2], cm3 = s_cmA[3];
            int wmin, wmax;
            if (hmax < 0) {   // empty: argmax-of-all-False semantics
                hmin = 0; hmax = HH - 1; wmin = 0; wmax = WW - 1;
            } else {
                if (cm0)      wmin = __ffsll((long long)cm0) - 1;
                else if (cm1) wmin = 64  + __ffsll((long long)cm1) - 1;
                else if (cm2) wmin = 128 + __ffsll((long long)cm2) - 1;
                else          wmin = 192 + __ffsll((long long)cm3) - 1;
                if (cm3)      wmax = 255 - __clzll((long long)cm3);
                else if (cm2) wmax = 191 - __clzll((long long)cm2);
                else if (cm1) wmax = 127 - __clzll((long long)cm1);
                else          wmax = 63  - __clzll((long long)cm0);
            }
            // rect columns [wmin, wmax)  (wmax EXCLUSIVE, matching reference slice)
            u64 rc0 = mask_lt(wmax, 0) & ~mask_lt(wmin, 0);
            u64 rc1 = mask_lt(wmax, 1) & ~mask_lt(wmin, 1);
            u64 rc2 = mask_lt(wmax, 2) & ~mask_lt(wmin, 2);
            u64 rc3 = mask_lt(wmax, 3) & ~mask_lt(wmin, 3);
            u64 diff = 0;
            for (int r = tid; r < HH; r += 128) {
                bool in = (r >= hmin) && (r <= hmax);
                u64 g0 = s_n[r][0] | (in ? rc0 : 0ull);
                u64 g1 = s_n[r][1] | (in ? rc1 : 0ull);
                u64 g2 = s_n[r][2] | (in ? rc2 : 0ull);
                u64 g3 = s_n[r][3] | (in ? rc3 : 0ull);
                diff |= (g0 ^ s_mask[r][0]) | (g1 ^ s_mask[r][1])
                      | (g2 ^ s_mask[r][2]) | (g3 ^ s_mask[r][3]);
                s_mask[r][0] = g0; s_mask[r][1] = g1;
                s_mask[r][2] = g2; s_mask[r][3] = g3;
                // reconstruct next row's new mask locally (s_n written before barrier)
                u64 n0, n1, n2, n3;
                if (r < HH - 2) {
                    bool in1 = (r + 1 >= hmin) && (r + 1 <= hmax);
                    n0 = s_n[r + 1][0] | (in1 ? rc0 : 0ull);
                    n1 = s_n[r + 1][1] | (in1 ? rc1 : 0ull);
                    n2 = s_n[r + 1][2] | (in1 ? rc2 : 0ull);
                    n3 = s_n[r + 1][3] | (in1 ? rc3 : 0ull);
                } else if (r == HH - 2) {
                    n0 = ~0ull; n1 = ~0ull; n2 = ~0ull; n3 = W3MASK;   // below(H-2)=gt
                } else {
                    n0 = n1 = n2 = n3 = 0ull;                           // below(H-1)=0
                }
                u64 bl0 = g0 & n0, bl1 = g1 & n1, bl2 = g2 & n2, bl3 = g3 & n3;
                u64 rt0 = ((g0 >> 1) | (g1 << 63)) & g0;
                u64 rt1 = ((g1 >> 1) | (g2 << 63)) & g1;
                u64 rt2 = ((g2 >> 1) | (g3 << 63)) & g2;
                u64 rt3 = ((g3 >> 1) | (1ull << 30)) & g3;
                s_b1[r][0] = bl0 ^ rt0; s_b1[r][1] = bl1 ^ rt1;
                s_b1[r][2] = bl2 ^ rt2; s_b1[r][3] = bl3 ^ rt3;
                s_b2[r][0] = bl0 & rt0; s_b2[r][1] = bl1 & rt1;
                s_b2[r][2] = bl2 & rt2; s_b2[r][3] = bl3 & rt3;
                int fl = (((bl0 | rt0) | (bl1 | rt1) | (bl2 | rt2) | (bl3 | rt3)) == 0ull) ? 2 : 0;
                if (r >= 1 && r <= HH - 3) {
                    bool inm = (r - 1 >= hmin) && (r - 1 <= hmax);
                    u64 m0 = s_n[r - 1][0] | (inm ? rc0 : 0ull);
                    u64 m1 = s_n[r - 1][1] | (inm ? rc1 : 0ull);
                    u64 m2 = s_n[r - 1][2] | (inm ? rc2 : 0ull);
                    u64 m3 = s_n[r - 1][3] | (inm ? rc3 : 0ull);
                    u64 d = (m0 ^ g0) | (m1 ^ g1) | (m2 ^ g2) | (m3 ^ g3)
                          | (g0 ^ n0) | (g1 ^ n1) | (g2 ^ n2) | (g3 ^ n3);
                    fl |= (d == 0ull) ? 1 : 0;
                }
                s_flags[r] = fl;
            }
            if (diff) s_chg2[pass & 1] = 1;   // benign multi-writer race (all write 1)
        }
        __syncthreads();   // B3

        if (!s_chg2[pass & 1]) break;   // converged: pass(m)==m (uniform decision)

        if (tid == 0) {   // safe: peers wait at B1 of next pass before touching these
            s_cmA[0] = s_cmA[1] = s_cmA[2] = s_cmA[3] = 0ull;
            s_hminA = 1 << 30; s_hmaxA = -1;
        }
    }

    // ---- unpack to float ----
    for (int r = warp; r < HH; r += 4) {
#pragma unroll
        for (int c = 0; c < 7; c++) {
            int w = c * 32 + lane;
            oi[r * WW + w] = (float)((s_mask[r][w >> 6] >> (w & 63)) & 1ull);
        }
    }
}

extern "C" void kernel_launch(void* const* d_in, const int* in_sizes, int n_in,
                              void* d_out, int out_size) {
    const float* x = (const float*)d_in[0];
    float* out = (float*)d_out;
    int nimg = in_sizes[0] / IMG;   // B*C = 8
    mask_ca_kernel<<<nimg, 128>>>(x, out);
}

// round 7
// speedup vs baseline: 1.0753x; 1.0753x over previous
#include <cuda_runtime.h>

typedef unsigned long long u64;

#define HH 224
#define WW 224
#define IMG (HH * WW)
#define NPASS 9
#define W3MASK 0xFFFFFFFFull

// bits 0..k-1 of word j (j*64 .. j*64+63) of a 224-bit mask
__device__ __forceinline__ u64 mask_lt(int k, int j) {
    int lo = j * 64;
    if (k <= lo) return 0ull;
    if (k >= lo + 64) return ~0ull;
    return (1ull << (k - lo)) - 1ull;
}

__global__ __launch_bounds__(128) void mask_ca_kernel(const float* __restrict__ x,
                                                      float* __restrict__ out) {
    __shared__ u64 s_mask[HH][4];   // current mask (post rect-fill)
    __shared__ u64 s_b1[HH][4];     // base == exactly one of below/right
    __shared__ u64 s_b2[HH][4];     // base == both
    __shared__ u64 s_n[HH][4];      // serial-scan output (pre rect-fill)
    __shared__ int s_flags[HH];     // bit0: g(r-1)==g(r)==g(r+1); bit1: (b1|b2)==0
    __shared__ u64 s_rect[4];
    __shared__ int s_hmin, s_hmax;
    __shared__ int s_chg[NPASS];    // write-once per pass (no reset race)

    const int tid  = threadIdx.x;
    const int lane = tid & 31;
    const int warp = tid >> 5;
    const float* xi = x + (size_t)blockIdx.x * IMG;
    float* oi = out + (size_t)blockIdx.x * IMG;

    // ---- pack input: threshold > 0.8 into 224-bit rows (4x u64) ----
    for (int r = warp; r < HH; r += 4) {
        const float* row = xi + r * WW;
        unsigned b[7];
#pragma unroll
        for (int c = 0; c < 7; c++)
            b[c] = __ballot_sync(0xFFFFFFFFu, row[c * 32 + lane] > 0.8f);
        if (lane == 0) {
            s_mask[r][0] = (u64)b[0] | ((u64)b[1] << 32);
            s_mask[r][1] = (u64)b[2] | ((u64)b[3] << 32);
            s_mask[r][2] = (u64)b[4] | ((u64)b[5] << 32);
            s_mask[r][3] = (u64)b[6];
        }
    }
    if (tid == 0) {
#pragma unroll
        for (int p = 0; p < NPASS; p++) s_chg[p] = 0;
    }
    __syncthreads();

    // ---- initial b1/b2 + flags from packed input ----
    for (int r = tid; r < HH; r += 128) {
        u64 g0 = s_mask[r][0], g1 = s_mask[r][1], g2 = s_mask[r][2], g3 = s_mask[r][3];
        u64 n0, n1, n2, n3;
        if (r < HH - 2) {
            n0 = s_mask[r + 1][0]; n1 = s_mask[r + 1][1];
            n2 = s_mask[r + 1][2]; n3 = s_mask[r + 1][3];
        } else if (r == HH - 2) {
            n0 = ~0ull; n1 = ~0ull; n2 = ~0ull; n3 = W3MASK;   // below(H-2)=gt
        } else {
            n0 = n1 = n2 = n3 = 0ull;                           // below(H-1)=0
        }
        u64 bl0 = g0 & n0, bl1 = g1 & n1, bl2 = g2 & n2, bl3 = g3 & n3;
        u64 rt0 = ((g0 >> 1) | (g1 << 63)) & g0;
        u64 rt1 = ((g1 >> 1) | (g2 << 63)) & g1;
        u64 rt2 = ((g2 >> 1) | (g3 << 63)) & g2;
        u64 rt3 = ((g3 >> 1) | (1ull << 30)) & g3;   // right(W-2)=gt, right(W-1)=0
        s_b1[r][0] = bl0 ^ rt0; s_b1[r][1] = bl1 ^ rt1;
        s_b1[r][2] = bl2 ^ rt2; s_b1[r][3] = bl3 ^ rt3;
        s_b2[r][0] = bl0 & rt0; s_b2[r][1] = bl1 & rt1;
        s_b2[r][2] = bl2 & rt2; s_b2[r][3] = bl3 & rt3;
        int fl = (((bl0 | rt0) | (bl1 | rt1) | (bl2 | rt2) | (bl3 | rt3)) == 0ull) ? 2 : 0;
        if (r >= 1 && r <= HH - 3) {
            u64 m0 = s_mask[r - 1][0], m1 = s_mask[r - 1][1];
            u64 m2 = s_mask[r - 1][2], m3 = s_mask[r - 1][3];
            u64 d = (m0 ^ g0) | (m1 ^ g1) | (m2 ^ g2) | (m3 ^ g3)
                  | (g0 ^ n0) | (g1 ^ n1) | (g2 ^ n2) | (g3 ^ n3);
            fl |= (d == 0ull) ? 1 : 0;
        }
        s_flags[r] = fl;
    }
    __syncthreads();

    for (int pass = 0; pass < NPASS; pass++) {
        // ---- serial raster recurrence (thread 0) ----
        if (tid == 0) {
            u64 p10 = ~0ull, p11 = ~0ull, p12 = ~0ull, p13 = W3MASK;  // virtual row -1 = ones
            u64 p20 = 0, p21 = 0, p22 = 0, p23 = 0;                   // virtual row -2 = zeros
            u64 cm0 = 0, cm1 = 0, cm2 = 0, cm3 = 0;
            int hmin = -1, hmax = -1;
            int e1 = 0, e2 = 0;   // nn(r-1)==nn(r-2), nn(r-2)==nn(r-3)
            int p1z = 0;          // nn(r-1) == 0
            int nzflag = 0;       // nn(r-1) nonzero
            for (int r = 0; r < HH; r++) {
                const int fl = s_flags[r];
                if (fl & 2) {
                    // zero row: b1|b2==0 -> nn=0 for ANY ab (O=0 keeps seed empty)
                    s_n[r][0] = 0ull; s_n[r][1] = 0ull; s_n[r][2] = 0ull; s_n[r][3] = 0ull;
                    e2 = e1; e1 = p1z; p1z = 1; nzflag = 0;
                    p20 = p10; p21 = p11; p22 = p12; p23 = p13;
                    p10 = 0ull; p11 = 0ull; p12 = 0ull; p13 = 0ull;
                    continue;
                }
                if (e1 & e2 & fl) {
                    // hit: b(r)==b(r-1) and ab(r)==ab(r-1) => nn(r)==nn(r-1)==p1
                    s_n[r][0] = p10; s_n[r][1] = p11; s_n[r][2] = p12; s_n[r][3] = p13;
                    if (nzflag) hmax = r;          // hmin/cm already reflect this value
                    p20 = p10; p21 = p11; p22 = p12; p23 = p13;   // p1 unchanged
                    e2 = e1; e1 = 1;                              // p1z unchanged
                    continue;
                }
                u64 ab0 = p10 & p20, ab1 = p11 & p21, ab2 = p12 & p22, ab3 = p13 & p23;
                u64 b10 = s_b1[r][0], b11 = s_b1[r][1], b12 = s_b1[r][2], b13 = s_b1[r][3];
                u64 b20 = s_b2[r][0], b21 = s_b2[r][1], b22 = s_b2[r][2], b23 = s_b2[r][3];
                // a = base + above; O: a>=2, P: a==1
                u64 O0 = b20 | (b10 & ab0), O1 = b21 | (b11 & ab1);
                u64 O2 = b22 | (b12 & ab2), O3 = b23 | (b13 & ab3);
                u64 P0 = (b10 ^ ab0) & ~b20, P1 = (b11 ^ ab1) & ~b21;
                u64 P2 = (b12 ^ ab2) & ~b22, P3 = (b13 ^ ab3) & ~b23;
                u64 F0 = 0, F1 = 0, F2 = 0, F3 = 0;
                if (P0 | P1 | P2 | P3) {
                    // run starts: S = P & ~(P<<1)   (virtual P(-1)=0)
                    u64 S0 = P0 & ~(P0 << 1);
                    u64 S1 = P1 & ~((P1 << 1) | (P0 >> 63));
                    u64 S2 = P2 & ~((P2 << 1) | (P1 >> 63));
                    u64 S3 = P3 & ~((P3 << 1) | (P2 >> 63));
                    // seed: runs whose carry-in n(s-1)&n(s-2)==1 under k=O
                    // virtual n(-1)=1, n(-2)=0
                    u64 gs0 = S0 & ((O0 << 1) | 1ull) & ((O0 << 2) | 2ull);
                    u64 gs1 = S1 & ((O1 << 1) | (O0 >> 63)) & ((O1 << 2) | (O0 >> 62));
                    u64 gs2 = S2 & ((O2 << 1) | (O1 >> 63)) & ((O2 << 2) | (O1 >> 62));
                    u64 gs3 = S3 & ((O3 << 1) | (O2 >> 63)) & ((O3 << 2) | (O2 >> 62));
                    if (gs0 | gs1 | gs2 | gs3) {
                        // gs monotone; F is a pure function of gs -> iterate on gs
                        for (int it = 0; it < 256; it++) {
                            // 224-bit add: sum = P + gs (ripple flips seeded runs to 0)
                            u64 s0 = P0 + gs0; u64 cy = (s0 < P0);
                            u64 u1 = P1 + cy; u64 cA = (u1 < P1);
                            u64 s1 = u1 + gs1; cy = cA | (s1 < u1);
                            u64 u2 = P2 + cy; cA = (u2 < P2);
                            u64 s2 = u2 + gs2; cy = cA | (s2 < u2);
                            u64 s3 = P3 + gs3 + cy;
                            F0 = P0 & ~s0; F1 = P1 & ~s1; F2 = P2 & ~s2; F3 = P3 & ~s3;
                            u64 k0 = O0 | F0, k1 = O1 | F1, k2 = O2 | F2, k3 = O3 | F3;
                            u64 gn0 = S0 & ((k0 << 1) | 1ull) & ((k0 << 2) | 2ull);
                            u64 gn1 = S1 & ((k1 << 1) | (k0 >> 63)) & ((k1 << 2) | (k0 >> 62));
                            u64 gn2 = S2 & ((k2 << 1) | (k1 >> 63)) & ((k2 << 2) | (k1 >> 62));
                            u64 gn3 = S3 & ((k3 << 1) | (k2 >> 63)) & ((k3 << 2) | (k2 >> 62));
                            u64 ch = (gn0 ^ gs0) | (gn1 ^ gs1) | (gn2 ^ gs2) | (gn3 ^ gs3);
                            if (!ch) break;
                            gs0 = gn0; gs1 = gn1; gs2 = gn2; gs3 = gn3;
                        }
                    }
                }
                u64 nn0 = O0 | F0, nn1 = O1 | F1, nn2 = O2 | F2, nn3 = O3 | F3;
                s_n[r][0] = nn0; s_n[r][1] = nn1; s_n[r][2] = nn2; s_n[r][3] = nn3;
                u64 de = (nn0 ^ p10) | (nn1 ^ p11) | (nn2 ^ p12) | (nn3 ^ p13);
                e2 = e1; e1 = (de == 0ull);
                u64 nz = nn0 | nn1 | nn2 | nn3;
                p1z = (nz == 0ull);
                if (nz) {
                    if (hmin < 0) hmin = r;
                    hmax = r;
                    cm0 |= nn0; cm1 |= nn1; cm2 |= nn2; cm3 |= nn3;
                    nzflag = 1;
                } else {
                    nzflag = 0;
                }
                p20 = p10; p21 = p11; p22 = p12; p23 = p13;
                p10 = nn0; p11 = nn1; p12 = nn2; p13 = nn3;
            }
            int wmin, wmax;
            if (hmin < 0) {   // empty: argmax-of-all-False semantics
                hmin = 0; hmax = HH - 1; wmin = 0; wmax = WW - 1;
            } else {
                if (cm0)      wmin = __ffsll((long long)cm0) - 1;
                else if (cm1) wmin = 64  + __ffsll((long long)cm1) - 1;
                else if (cm2) wmin = 128 + __ffsll((long long)cm2) - 1;
                else          wmin = 192 + __ffsll((long long)cm3) - 1;
                if (cm3)      wmax = 255 - __clzll((long long)cm3);
                else if (cm2) wmax = 191 - __clzll((long long)cm2);
                else if (cm1) wmax = 127 - __clzll((long long)cm1);
                else          wmax = 63  - __clzll((long long)cm0);
            }
            // rect columns [wmin, wmax)  (wmax EXCLUSIVE, matching reference slice)
#pragma unroll
            for (int j = 0; j < 4; j++)
                s_rect[j] = mask_lt(wmax, j) & ~mask_lt(wmin, j);
            s_hmin = hmin; s_hmax = hmax;
        }
        __syncthreads();

        // ---- fused parallel phase: rect + change-detect + next b1/b2 + next flags ----
        {
            const int hmin = s_hmin, hmax = s_hmax;
            const u64 rc0 = s_rect[0], rc1 = s_rect[1], rc2 = s_rect[2], rc3 = s_rect[3];
            u64 diff = 0;
            for (int r = tid; r < HH; r += 128) {
                bool in = (r >= hmin) && (r <= hmax);
                u64 g0 = s_n[r][0] | (in ? rc0 : 0ull);
                u64 g1 = s_n[r][1] | (in ? rc1 : 0ull);
                u64 g2 = s_n[r][2] | (in ? rc2 : 0ull);
                u64 g3 = s_n[r][3] | (in ? rc3 : 0ull);
                diff |= (g0 ^ s_mask[r][0]) | (g1 ^ s_mask[r][1])
                      | (g2 ^ s_mask[r][2]) | (g3 ^ s_mask[r][3]);
                s_mask[r][0] = g0; s_mask[r][1] = g1;
                s_mask[r][2] = g2; s_mask[r][3] = g3;
                // reconstruct next row's new mask locally (s_n written before barrier)
                u64 n0, n1, n2, n3;
                if (r < HH - 2) {
                    bool in1 = (r + 1 >= hmin) && (r + 1 <= hmax);
                    n0 = s_n[r + 1][0] | (in1 ? rc0 : 0ull);
                    n1 = s_n[r + 1][1] | (in1 ? rc1 : 0ull);
                    n2 = s_n[r + 1][2] | (in1 ? rc2 : 0ull);
                    n3 = s_n[r + 1][3] | (in1 ? rc3 : 0ull);
                } else if (r == HH - 2) {
                    n0 = ~0ull; n1 = ~0ull; n2 = ~0ull; n3 = W3MASK;   // below(H-2)=gt
                } else {
                    n0 = n1 = n2 = n3 = 0ull;                           // below(H-1)=0
                }
                u64 bl0 = g0 & n0, bl1 = g1 & n1, bl2 = g2 & n2, bl3 = g3 & n3;
                u64 rt0 = ((g0 >> 1) | (g1 << 63)) & g0;
                u64 rt1 = ((g1 >> 1) | (g2 << 63)) & g1;
                u64 rt2 = ((g2 >> 1) | (g3 << 63)) & g2;
                u64 rt3 = ((g3 >> 1) | (1ull << 30)) & g3;
                s_b1[r][0] = bl0 ^ rt0; s_b1[r][1] = bl1 ^ rt1;
                s_b1[r][2] = bl2 ^ rt2; s_b1[r][3] = bl3 ^ rt3;
                s_b2[r][0] = bl0 & rt0; s_b2[r][1] = bl1 & rt1;
                s_b2[r][2] = bl2 & rt2; s_b2[r][3] = bl3 & rt3;
                int fl = (((bl0 | rt0) | (bl1 | rt1) | (bl2 | rt2) | (bl3 | rt3)) == 0ull) ? 2 : 0;
                if (r >= 1 && r <= HH - 3) {
                    bool inm = (r - 1 >= hmin) && (r - 1 <= hmax);
                    u64 m0 = s_n[r - 1][0] | (inm ? rc0 : 0ull);
                    u64 m1 = s_n[r - 1][1] | (inm ? rc1 : 0ull);
                    u64 m2 = s_n[r - 1][2] | (inm ? rc2 : 0ull);
                    u64 m3 = s_n[r - 1][3] | (inm ? rc3 : 0ull);
                    u64 d = (m0 ^ g0) | (m1 ^ g1) | (m2 ^ g2) | (m3 ^ g3)
                          | (g0 ^ n0) | (g1 ^ n1) | (g2 ^ n2) | (g3 ^ n3);
                    fl |= (d == 0ull) ? 1 : 0;
                }
                s_flags[r] = fl;
            }
            if (diff) s_chg[pass] = 1;   // benign multi-writer race (all write 1)
        }
        __syncthreads();

        // converged: pass(m)==m, all remaining passes are identity
        if (!s_chg[pass]) break;   // write-once flag: no reset, no race
    }

    // ---- unpack to float ----
    for (int r = warp; r < HH; r += 4) {
#pragma unroll
        for (int c = 0; c < 7; c++) {
            int w = c * 32 + lane;
            oi[r * WW + w] = (float)((s_mask[r][w >> 6] >> (w & 63)) & 1ull);
        }
    }
}

extern "C" void kernel_launch(void* const* d_in, const int* in_sizes, int n_in,
                              void* d_out, int out_size) {
    const float* x = (const float*)d_in[0];
    float* out = (float*)d_out;
    int nimg = in_sizes[0] / IMG;   // B*C = 8
    mask_ca_kernel<<<nimg, 128>>>(x, out);
}

// round 9
// speedup vs baseline: 1.2097x; 1.1250x over previous
#include <cuda_runtime.h>

typedef unsigned long long u64;
typedef unsigned int u32;

#define HH 224
#define WW 224
#define IMG (HH * WW)
#define NPASS 9
#define W3MASK 0xFFFFFFFFull

// bits 0..k-1 of word j (j*64 .. j*64+63) of a 224-bit mask
__device__ __forceinline__ u64 mask_lt(int k, int j) {
    int lo = j * 64;
    if (k <= lo) return 0ull;
    if (k >= lo + 64) return ~0ull;
    return (1ull << (k - lo)) - 1ull;
}

__global__ __launch_bounds__(128) void mask_ca_kernel(const float* __restrict__ x,
                                                      float* __restrict__ out) {
    __shared__ u64 s_mask[HH][4];   // current mask (post rect-fill)
    __shared__ u64 s_b1[HH][4];     // base == exactly one of below/right
    __shared__ u64 s_b2[HH][4];     // base == both
    __shared__ u64 s_n[HH][4];      // serial-scan output (pre rect-fill), sparse via s_src
    __shared__ int s_src[HH];       // representative row: value of row r is s_n[s_src[r]]
    __shared__ u32 s_fmap[8];       // bit r: g(r-1)==g(r)==g(r+1) (=> b(r)==b(r-1))
    __shared__ u32 s_zmap[8];       // bit r: (b1|b2)==0 at row r
    __shared__ u64 s_rect[4];
    __shared__ int s_hmin, s_hmax;
    __shared__ int s_chg[NPASS];    // write-once per pass (no reset race)

    const int tid  = threadIdx.x;
    const int lane = tid & 31;
    const int warp = tid >> 5;
    const float* xi = x + (size_t)blockIdx.x * IMG;
    float* oi = out + (size_t)blockIdx.x * IMG;

    // ---- pack input: threshold > 0.8 into 224-bit rows (4x u64) ----
    for (int r = warp; r < HH; r += 4) {
        const float* row = xi + r * WW;
        unsigned b[7];
#pragma unroll
        for (int c = 0; c < 7; c++)
            b[c] = __ballot_sync(0xFFFFFFFFu, row[c * 32 + lane] > 0.8f);
        if (lane == 0) {
            s_mask[r][0] = (u64)b[0] | ((u64)b[1] << 32);
            s_mask[r][1] = (u64)b[2] | ((u64)b[3] << 32);
            s_mask[r][2] = (u64)b[4] | ((u64)b[5] << 32);
            s_mask[r][3] = (u64)b[6];
        }
    }
    if (tid == 0) {
#pragma unroll
        for (int p = 0; p < NPASS; p++) s_chg[p] = 0;
    }
    __syncthreads();

    // ---- initial b1/b2 + flag bitmaps from packed input ----
    // One row per thread: iter A covers rows 0..127, iter B rows 128..223 (warps 0-2).
#define INIT_ROW(RR, FLOUT) do {                                               \
        const int r_ = (RR);                                                   \
        u64 g0 = s_mask[r_][0], g1 = s_mask[r_][1];                            \
        u64 g2 = s_mask[r_][2], g3 = s_mask[r_][3];                            \
        u64 n0, n1, n2, n3;                                                    \
        if (r_ < HH - 2) {                                                     \
            n0 = s_mask[r_ + 1][0]; n1 = s_mask[r_ + 1][1];                    \
            n2 = s_mask[r_ + 1][2]; n3 = s_mask[r_ + 1][3];                    \
        } else if (r_ == HH - 2) {                                             \
            n0 = ~0ull; n1 = ~0ull; n2 = ~0ull; n3 = W3MASK;                   \
        } else { n0 = n1 = n2 = n3 = 0ull; }                                   \
        u64 bl0 = g0 & n0, bl1 = g1 & n1, bl2 = g2 & n2, bl3 = g3 & n3;        \
        u64 rt0 = ((g0 >> 1) | (g1 << 63)) & g0;                               \
        u64 rt1 = ((g1 >> 1) | (g2 << 63)) & g1;                               \
        u64 rt2 = ((g2 >> 1) | (g3 << 63)) & g2;                               \
        u64 rt3 = ((g3 >> 1) | (1ull << 30)) & g3;                             \
        s_b1[r_][0] = bl0 ^ rt0; s_b1[r_][1] = bl1 ^ rt1;                      \
        s_b1[r_][2] = bl2 ^ rt2; s_b1[r_][3] = bl3 ^ rt3;                      \
        s_b2[r_][0] = bl0 & rt0; s_b2[r_][1] = bl1 & rt1;                      \
        s_b2[r_][2] = bl2 & rt2; s_b2[r_][3] = bl3 & rt3;                      \
        int fl_ = (((bl0 | rt0) | (bl1 | rt1) | (bl2 | rt2) | (bl3 | rt3))     \
                   == 0ull) ? 2 : 0;                                           \
        if (r_ >= 1 && r_ <= HH - 3) {                                         \
            u64 m0 = s_mask[r_ - 1][0], m1 = s_mask[r_ - 1][1];                \
            u64 m2 = s_mask[r_ - 1][2], m3 = s_mask[r_ - 1][3];                \
            u64 d = (m0 ^ g0) | (m1 ^ g1) | (m2 ^ g2) | (m3 ^ g3)              \
                  | (g0 ^ n0) | (g1 ^ n1) | (g2 ^ n2) | (g3 ^ n3);             \
            fl_ |= (d == 0ull) ? 1 : 0;                                        \
        }                                                                      \
        FLOUT = fl_;                                                           \
    } while (0)

    {
        int fl;
        INIT_ROW(tid, fl);
        u32 f1 = __ballot_sync(0xFFFFFFFFu, fl & 1);
        u32 f2 = __ballot_sync(0xFFFFFFFFu, fl & 2);
        if (lane == 0) { s_fmap[warp] = f1; s_zmap[warp] = f2; }
    }
    if (tid < 96) {
        int fl;
        INIT_ROW(128 + tid, fl);
        u32 f1 = __ballot_sync(0xFFFFFFFFu, fl & 1);
        u32 f2 = __ballot_sync(0xFFFFFFFFu, fl & 2);
        if (lane == 0) { s_fmap[4 + warp] = f1; s_zmap[4 + warp] = f2; }
    }
    __syncthreads();

    for (int pass = 0; pass < NPASS; pass++) {
        // ---- serial raster recurrence (thread 0) ----
        if (tid == 0) {
            u32 fm[7], zm[7];
#pragma unroll
            for (int j = 0; j < 7; j++) { fm[j] = s_fmap[j]; zm[j] = s_zmap[j]; }
            u64 p10 = ~0ull, p11 = ~0ull, p12 = ~0ull, p13 = W3MASK;  // virtual row -1
            u64 p20 = 0, p21 = 0, p22 = 0, p23 = 0;                   // virtual row -2
            u64 cm0 = 0, cm1 = 0, cm2 = 0, cm3 = 0;
            int hmin = -1, hmax = -1;
            int e1 = 0, e2 = 0;   // nn(r-1)==nn(r-2), nn(r-2)==nn(r-3)
            int p1z = 0;          // nn(r-1) == 0
            int nzflag = 0;       // nn(r-1) nonzero
            int r0 = 0;           // last row with s_n actually written
            int r = 0;
            while (r < HH) {
                const int w = r >> 5, bpos = r & 31;
                if ((e1 & e2) && ((fm[w] >> bpos) & 1)) {
                    // hit RUN: consecutive rows with b(q)==b(q-1); nn stays == p1
                    int end;
                    u32 xbits = (~fm[w]) >> bpos;
                    if (xbits) end = r + __ffs(xbits) - 1;
                    else {
                        int ww = w + 1;
                        while (ww < 7 && fm[ww] == 0xFFFFFFFFu) ww++;
                        end = (ww < 7) ? ww * 32 + __ffs(~fm[ww]) - 1 : HH;
                    }
                    if (end > HH) end = HH;
                    for (int q = r; q < end; q++) s_src[q] = r0;
                    if (nzflag) hmax = end - 1;   // hmin/cm already reflect this value
                    // state (p1,p2,e1,e2,p1z,nzflag) unchanged across the run
                    r = end;
                    continue;
                }
                if ((zm[w] >> bpos) & 1) {
                    // zero row: b1|b2==0 -> nn=0 for ANY ab (O=0 keeps seed empty)
                    s_n[r][0] = 0ull; s_n[r][1] = 0ull; s_n[r][2] = 0ull; s_n[r][3] = 0ull;
                    s_src[r] = r; r0 = r;
                    e2 = e1; e1 = p1z; p1z = 1; nzflag = 0;
                    p20 = p10; p21 = p11; p22 = p12; p23 = p13;
                    p10 = 0ull; p11 = 0ull; p12 = 0ull; p13 = 0ull;
                    r++;
                    continue;
                }
                // ---- miss: full row computation ----
                u64 ab0 = p10 & p20, ab1 = p11 & p21, ab2 = p12 & p22, ab3 = p13 & p23;
                u64 b10 = s_b1[r][0], b11 = s_b1[r][1], b12 = s_b1[r][2], b13 = s_b1[r][3];
                u64 b20 = s_b2[r][0], b21 = s_b2[r][1], b22 = s_b2[r][2], b23 = s_b2[r][3];
                // a = base + above; O: a>=2, P: a==1
                u64 O0 = b20 | (b10 & ab0), O1 = b21 | (b11 & ab1);
                u64 O2 = b22 | (b12 & ab2), O3 = b23 | (b13 & ab3);
                u64 P0 = (b10 ^ ab0) & ~b20, P1 = (b11 ^ ab1) & ~b21;
                u64 P2 = (b12 ^ ab2) & ~b22, P3 = (b13 ^ ab3) & ~b23;
                u64 F0 = 0, F1 = 0, F2 = 0, F3 = 0;
                if (P0 | P1 | P2 | P3) {
                    // run starts: S = P & ~(P<<1)   (virtual P(-1)=0)
                    u64 S0 = P0 & ~(P0 << 1);
                    u64 S1 = P1 & ~((P1 << 1) | (P0 >> 63));
                    u64 S2 = P2 & ~((P2 << 1) | (P1 >> 63));
                    u64 S3 = P3 & ~((P3 << 1) | (P2 >> 63));
                    // seed: runs whose carry-in n(s-1)&n(s-2)==1 under k=O
                    // virtual n(-1)=1, n(-2)=0
                    u64 gs0 = S0 & ((O0 << 1) | 1ull) & ((O0 << 2) | 2ull);
                    u64 gs1 = S1 & ((O1 << 1) | (O0 >> 63)) & ((O1 << 2) | (O0 >> 62));
                    u64 gs2 = S2 & ((O2 << 1) | (O1 >> 63)) & ((O2 << 2) | (O1 >> 62));
                    u64 gs3 = S3 & ((O3 << 1) | (O2 >> 63)) & ((O3 << 2) | (O2 >> 62));
                    if (gs0 | gs1 | gs2 | gs3) {
                        // gs monotone; F is a pure function of gs -> iterate on gs
                        for (int it = 0; it < 256; it++) {
                            // 224-bit add: sum = P + gs (ripple flips seeded runs to 0)
                            u64 s0 = P0 + gs0; u64 cy = (s0 < P0);
                            u64 u1 = P1 + cy; u64 cA = (u1 < P1);
                            u64 s1 = u1 + gs1; cy = cA | (s1 < u1);
                            u64 u2 = P2 + cy; cA = (u2 < P2);
                            u64 s2 = u2 + gs2; cy = cA | (s2 < u2);
                            u64 s3 = P3 + gs3 + cy;
                            F0 = P0 & ~s0; F1 = P1 & ~s1; F2 = P2 & ~s2; F3 = P3 & ~s3;
                            u64 k0 = O0 | F0, k1 = O1 | F1, k2 = O2 | F2, k3 = O3 | F3;
                            u64 gn0 = S0 & ((k0 << 1) | 1ull) & ((k0 << 2) | 2ull);
                            u64 gn1 = S1 & ((k1 << 1) | (k0 >> 63)) & ((k1 << 2) | (k0 >> 62));
                            u64 gn2 = S2 & ((k2 << 1) | (k1 >> 63)) & ((k2 << 2) | (k1 >> 62));
                            u64 gn3 = S3 & ((k3 << 1) | (k2 >> 63)) & ((k3 << 2) | (k2 >> 62));
                            u64 ch = (gn0 ^ gs0) | (gn1 ^ gs1) | (gn2 ^ gs2) | (gn3 ^ gs3);
                            if (!ch) break;
                            gs0 = gn0; gs1 = gn1; gs2 = gn2; gs3 = gn3;
                        }
                    }
                }
                u64 nn0 = O0 | F0, nn1 = O1 | F1, nn2 = O2 | F2, nn3 = O3 | F3;
                s_n[r][0] = nn0; s_n[r][1] = nn1; s_n[r][2] = nn2; s_n[r][3] = nn3;
                s_src[r] = r; r0 = r;
                u64 de = (nn0 ^ p10) | (nn1 ^ p11) | (nn2 ^ p12) | (nn3 ^ p13);
                e2 = e1; e1 = (de == 0ull);
                u64 nz = nn0 | nn1 | nn2 | nn3;
                p1z = (nz == 0ull);
                if (nz) {
                    if (hmin < 0) hmin = r;
                    hmax = r;
                    cm0 |= nn0; cm1 |= nn1; cm2 |= nn2; cm3 |= nn3;
                    nzflag = 1;
                } else {
                    nzflag = 0;
                }
                p20 = p10; p21 = p11; p22 = p12; p23 = p13;
                p10 = nn0; p11 = nn1; p12 = nn2; p13 = nn3;
                r++;
            }
            int wmin, wmax;
            if (hmin < 0) {   // empty: argmax-of-all-False semantics
                hmin = 0; hmax = HH - 1; wmin = 0; wmax = WW - 1;
            } else {
                if (cm0)      wmin = __ffsll((long long)cm0) - 1;
                else if (cm1) wmin = 64  + __ffsll((long long)cm1) - 1;
                else if (cm2) wmin = 128 + __ffsll((long long)cm2) - 1;
                else          wmin = 192 + __ffsll((long long)cm3) - 1;
                if (cm3)      wmax = 255 - __clzll((long long)cm3);
                else if (cm2) wmax = 191 - __clzll((long long)cm2);
                else if (cm1) wmax = 127 - __clzll((long long)cm1);
                else          wmax = 63  - __clzll((long long)cm0);
            }
            // rect columns [wmin, wmax)  (wmax EXCLUSIVE, matching reference slice)
#pragma unroll
            for (int j = 0; j < 4; j++)
                s_rect[j] = mask_lt(wmax, j) & ~mask_lt(wmin, j);
            s_hmin = hmin; s_hmax = hmax;
        }
        __syncthreads();

        // ---- fused parallel phase: rect + diff + next b1/b2 + next flag bitmaps ----
        {
            const int hmin = s_hmin, hmax = s_hmax;
            const u64 rc0 = s_rect[0], rc1 = s_rect[1], rc2 = s_rect[2], rc3 = s_rect[3];
            u64 diff = 0;

#define PHASEB_ROW(RR, FLOUT) do {                                             \
        const int r_ = (RR);                                                   \
        const int sr_ = s_src[r_];                                             \
        bool in_ = (r_ >= hmin) && (r_ <= hmax);                               \
        u64 g0 = s_n[sr_][0] | (in_ ? rc0 : 0ull);                             \
        u64 g1 = s_n[sr_][1] | (in_ ? rc1 : 0ull);                             \
        u64 g2 = s_n[sr_][2] | (in_ ? rc2 : 0ull);                             \
        u64 g3 = s_n[sr_][3] | (in_ ? rc3 : 0ull);                             \
        diff |= (g0 ^ s_mask[r_][0]) | (g1 ^ s_mask[r_][1])                    \
              | (g2 ^ s_mask[r_][2]) | (g3 ^ s_mask[r_][3]);                   \
        s_mask[r_][0] = g0; s_mask[r_][1] = g1;                                \
        s_mask[r_][2] = g2; s_mask[r_][3] = g3;                                \
        u64 n0, n1, n2, n3;                                                    \
        if (r_ < HH - 2) {                                                     \
            const int sn_ = s_src[r_ + 1];                                     \
            bool in1_ = (r_ + 1 >= hmin) && (r_ + 1 <= hmax);                  \
            n0 = s_n[sn_][0] | (in1_ ? rc0 : 0ull);                            \
            n1 = s_n[sn_][1] | (in1_ ? rc1 : 0ull);                            \
            n2 = s_n[sn_][2] | (in1_ ? rc2 : 0ull);                            \
            n3 = s_n[sn_][3] | (in1_ ? rc3 : 0ull);                            \
        } else if (r_ == HH - 2) {                                             \
            n0 = ~0ull; n1 = ~0ull; n2 = ~0ull; n3 = W3MASK;                   \
        } else { n0 = n1 = n2 = n3 = 0ull; }                                   \
        u64 bl0 = g0 & n0, bl1 = g1 & n1, bl2 = g2 & n2, bl3 = g3 & n3;        \
        u64 rt0 = ((g0 >> 1) | (g1 << 63)) & g0;                               \
        u64 rt1 = ((g1 >> 1) | (g2 << 63)) & g1;                               \
        u64 rt2 = ((g2 >> 1) | (g3 << 63)) & g2;                               \
        u64 rt3 = ((g3 >> 1) | (1ull << 30)) & g3;                             \
        s_b1[r_][0] = bl0 ^ rt0; s_b1[r_][1] = bl1 ^ rt1;                      \
        s_b1[r_][2] = bl2 ^ rt2; s_b1[r_][3] = bl3 ^ rt3;                      \
        s_b2[r_][0] = bl0 & rt0; s_b2[r_][1] = bl1 & rt1;                      \
        s_b2[r_][2] = bl2 & rt2; s_b2[r_][3] = bl3 & rt3;                      \
        int fl_ = (((bl0 | rt0) | (bl1 | rt1) | (bl2 | rt2) | (bl3 | rt3))     \
                   == 0ull) ? 2 : 0;                                           \
        if (r_ >= 1 && r_ <= HH - 3) {                                         \
            const int sm_ = s_src[r_ - 1];                                     \
            bool inm_ = (r_ - 1 >= hmin) && (r_ - 1 <= hmax);                  \
            u64 m0 = s_n[sm_][0] | (inm_ ? rc0 : 0ull);                        \
            u64 m1 = s_n[sm_][1] | (inm_ ? rc1 : 0ull);                        \
            u64 m2 = s_n[sm_][2] | (inm_ ? rc2 : 0ull);                        \
            u64 m3 = s_n[sm_][3] | (inm_ ? rc3 : 0ull);                        \
            u64 d = (m0 ^ g0) | (m1 ^ g1) | (m2 ^ g2) | (m3 ^ g3)              \
                  | (g0 ^ n0) | (g1 ^ n1) | (g2 ^ n2) | (g3 ^ n3);             \
            fl_ |= (d == 0ull) ? 1 : 0;                                        \
        }                                                                      \
        FLOUT = fl_;                                                           \
    } while (0)

            {
                int fl;
                PHASEB_ROW(tid, fl);
                u32 f1 = __ballot_sync(0xFFFFFFFFu, fl & 1);
                u32 f2 = __ballot_sync(0xFFFFFFFFu, fl & 2);
                if (lane == 0) { s_fmap[warp] = f1; s_zmap[warp] = f2; }
            }
            if (tid < 96) {
                int fl;
                PHASEB_ROW(128 + tid, fl);
                u32 f1 = __ballot_sync(0xFFFFFFFFu, fl & 1);
                u32 f2 = __ballot_sync(0xFFFFFFFFu, fl & 2);
                if (lane == 0) { s_fmap[4 + warp] = f1; s_zmap[4 + warp] = f2; }
            }
            if (diff) s_chg[pass] = 1;   // benign multi-writer race (all write 1)
#undef PHASEB_ROW
        }
        __syncthreads();

        // converged: pass(m)==m, all remaining passes are identity
        if (!s_chg[pass]) break;   // write-once flag: no reset, no race
    }

    // ---- unpack to float ----
    for (int r = warp; r < HH; r += 4) {
#pragma unroll
        for (int c = 0; c < 7; c++) {
            int w = c * 32 + lane;
            oi[r * WW + w] = (float)((s_mask[r][w >> 6] >> (w & 63)) & 1ull);
        }
    }
}

extern "C" void kernel_launch(void* const* d_in, const int* in_sizes, int n_in,
                              void* d_out, int out_size) {
    const float* x = (const float*)d_in[0];
    float* out = (float*)d_out;
    int nimg = in_sizes[0] / IMG;   // B*C = 8
    mask_ca_kernel<<<nimg, 128>>>(x, out);
}

// round 11
// speedup vs baseline: 1.2114x; 1.0015x over previous
#include <cuda_runtime.h>

typedef unsigned long long u64;
typedef unsigned int u32;

#define HH 224
#define WW 224
#define IMG (HH * WW)
#define NPASS 9
#define W3MASK 0xFFFFFFFFull
#define FULLM 0xFFFFFFFFu

// bits 0..k-1 of word j (j*64 .. j*64+63) of a 224-bit mask
__device__ __forceinline__ u64 mask_lt(int k, int j) {
    int lo = j * 64;
    if (k <= lo) return 0ull;
    if (k >= lo + 64) return ~0ull;
    return (1ull << (k - lo)) - 1ull;
}

__global__ __launch_bounds__(128) void mask_ca_kernel(const float* __restrict__ x,
                                                      float* __restrict__ out) {
    __shared__ u64 s_mask[HH][4];   // current mask (post rect-fill)
    __shared__ u64 s_b1[HH][4];     // base == exactly one of below/right
    __shared__ u64 s_b2[HH][4];     // base == both
    __shared__ u64 s_n[HH][4];      // serial-scan output (pre rect-fill), sparse via s_src
    __shared__ int s_src[HH];       // representative row: value of row r is s_n[s_src[r]]
    __shared__ u32 s_fmap[8];       // bit r: g(r-1)==g(r)==g(r+1) (=> b(r)==b(r-1))
    __shared__ u32 s_zmap[8];       // bit r: (b1|b2)==0 at row r
    __shared__ u64 s_cmA[4];        // column-OR handoff, serial warp internal
    __shared__ u64 s_rect[4];
    __shared__ int s_hmin, s_hmax;
    __shared__ int s_chg[NPASS];    // write-once per pass (no reset race)

    const int tid  = threadIdx.x;
    const int lane = tid & 31;
    const int warp = tid >> 5;
    const float* xi = x + (size_t)blockIdx.x * IMG;
    float* oi = out + (size_t)blockIdx.x * IMG;

    // ---- pack input: threshold > 0.8 into 224-bit rows (4x u64) ----
    for (int r = warp; r < HH; r += 4) {
        const float* row = xi + r * WW;
        unsigned b[7];
#pragma unroll
        for (int c = 0; c < 7; c++)
            b[c] = __ballot_sync(FULLM, row[c * 32 + lane] > 0.8f);
        if (lane == 0) {
            s_mask[r][0] = (u64)b[0] | ((u64)b[1] << 32);
            s_mask[r][1] = (u64)b[2] | ((u64)b[3] << 32);
            s_mask[r][2] = (u64)b[4] | ((u64)b[5] << 32);
            s_mask[r][3] = (u64)b[6];
        }
    }
    if (tid == 0) {
#pragma unroll
        for (int p = 0; p < NPASS; p++) s_chg[p] = 0;
    }
    __syncthreads();

    // ---- initial b1/b2 + flag bitmaps from packed input ----
#define INIT_ROW(RR, FLOUT) do {                                               \
        const int r_ = (RR);                                                   \
        u64 g0 = s_mask[r_][0], g1 = s_mask[r_][1];                            \
        u64 g2 = s_mask[r_][2], g3 = s_mask[r_][3];                            \
        u64 n0, n1, n2, n3;                                                    \
        if (r_ < HH - 2) {                                                     \
            n0 = s_mask[r_ + 1][0]; n1 = s_mask[r_ + 1][1];                    \
            n2 = s_mask[r_ + 1][2]; n3 = s_mask[r_ + 1][3];                    \
        } else if (r_ == HH - 2) {                                             \
            n0 = ~0ull; n1 = ~0ull; n2 = ~0ull; n3 = W3MASK;                   \
        } else { n0 = n1 = n2 = n3 = 0ull; }                                   \
        u64 bl0 = g0 & n0, bl1 = g1 & n1, bl2 = g2 & n2, bl3 = g3 & n3;        \
        u64 rt0 = ((g0 >> 1) | (g1 << 63)) & g0;                               \
        u64 rt1 = ((g1 >> 1) | (g2 << 63)) & g1;                               \
        u64 rt2 = ((g2 >> 1) | (g3 << 63)) & g2;                               \
        u64 rt3 = ((g3 >> 1) | (1ull << 30)) & g3;                             \
        s_b1[r_][0] = bl0 ^ rt0; s_b1[r_][1] = bl1 ^ rt1;                      \
        s_b1[r_][2] = bl2 ^ rt2; s_b1[r_][3] = bl3 ^ rt3;                      \
        s_b2[r_][0] = bl0 & rt0; s_b2[r_][1] = bl1 & rt1;                      \
        s_b2[r_][2] = bl2 & rt2; s_b2[r_][3] = bl3 & rt3;                      \
        int fl_ = (((bl0 | rt0) | (bl1 | rt1) | (bl2 | rt2) | (bl3 | rt3))     \
                   == 0ull) ? 2 : 0;                                           \
        if (r_ >= 1 && r_ <= HH - 3) {                                         \
            u64 m0 = s_mask[r_ - 1][0], m1 = s_mask[r_ - 1][1];                \
            u64 m2 = s_mask[r_ - 1][2], m3 = s_mask[r_ - 1][3];                \
            u64 d = (m0 ^ g0) | (m1 ^ g1) | (m2 ^ g2) | (m3 ^ g3)              \
                  | (g0 ^ n0) | (g1 ^ n1) | (g2 ^ n2) | (g3 ^ n3);             \
            fl_ |= (d == 0ull) ? 1 : 0;                                        \
        }                                                                      \
        FLOUT = fl_;                                                           \
    } while (0)

    {
        int fl;
        INIT_ROW(tid, fl);
        u32 f1 = __ballot_sync(FULLM, fl & 1);
        u32 f2 = __ballot_sync(FULLM, fl & 2);
        if (lane == 0) { s_fmap[warp] = f1; s_zmap[warp] = f2; }
    }
    if (tid < 96) {
        int fl;
        INIT_ROW(128 + tid, fl);
        u32 f1 = __ballot_sync(FULLM, fl & 1);
        u32 f2 = __ballot_sync(FULLM, fl & 2);
        if (lane == 0) { s_fmap[4 + warp] = f1; s_zmap[4 + warp] = f2; }
    }
    __syncthreads();

    for (int pass = 0; pass < NPASS; pass++) {
        // ---- serial raster recurrence, warp-SIMD: word j=lane&3 per lane ----
        // All 8 lane-groups compute identical data, so every branch is uniform
        // and full-warp ballots/shfls are safe. State (p1,p2,cm) is lane-local.
        if (warp == 0) {
            const int j = lane & 3;
            u32 fm[7], zm[7];
#pragma unroll
            for (int jj = 0; jj < 7; jj++) { fm[jj] = s_fmap[jj]; zm[jj] = s_zmap[jj]; }
            u64 p1 = (j < 3) ? ~0ull : W3MASK;   // virtual row -1 = ones
            u64 p2 = 0ull;                        // virtual row -2 = zeros
            u64 cm = 0ull;
            int hmin = -1, hmax = -1;
            int e1 = 0, e2 = 0, p1z = 0, nzflag = 0, r0 = 0;
            int r = 0;
            while (r < HH) {
                const int w = r >> 5, bpos = r & 31;
                if ((e1 & e2) && ((fm[w] >> bpos) & 1)) {
                    // hit RUN: consecutive rows with b(q)==b(q-1); nn stays == p1
                    int end;
                    u32 xbits = (~fm[w]) >> bpos;
                    if (xbits) end = r + __ffs(xbits) - 1;
                    else {
                        int ww = w + 1;
                        while (ww < 7 && fm[ww] == FULLM) ww++;
                        end = (ww < 7) ? ww * 32 + __ffs(~fm[ww]) - 1 : HH;
                    }
                    if (end > HH) end = HH;
                    for (int q = r + lane; q < end; q += 32) s_src[q] = r0;
                    if (nzflag) hmax = end - 1;
                    r = end;
                    continue;
                }
                if ((zm[w] >> bpos) & 1) {
                    // zero row: b1|b2==0 -> nn=0 for ANY ab (O=0 keeps seed empty)
                    if (lane < 4) s_n[r][j] = 0ull;
                    if (lane == 0) s_src[r] = r;
                    r0 = r;
                    e2 = e1; e1 = p1z; p1z = 1; nzflag = 0;
                    p2 = p1; p1 = 0ull;
                    r++;
                    continue;
                }
                // ---- miss: full row, one 64-bit word per lane ----
                u64 ab = p1 & p2;
                u64 b1 = s_b1[r][j], b2 = s_b2[r][j];
                u64 O = b2 | (b1 & ab);      // a>=2
                u64 P = (b1 ^ ab) & ~b2;     // a==1
                u64 F = 0ull;
                u32 pb = __ballot_sync(FULLM, P != 0ull);
                if (pb) {
                    // cross-word bits from lane j-1: [2]=P63, [1]=O63, [0]=O62
                    u32 hi = ((u32)(P >> 63) << 2) | ((u32)(O >> 62) & 3u);
                    u32 hp = __shfl_up_sync(FULLM, hi, 1);
                    u32 sIn = (j == 0) ? 0u : ((hp >> 2) & 1u);
                    u32 aIn = (j == 0) ? 1u : ((hp >> 1) & 1u);   // virtual n(-1)=1
                    u32 cIn = (j == 0) ? 2u : (hp & 3u);          // virtual n(-2)=0
                    u64 S  = P & ~((P << 1) | (u64)sIn);          // run starts
                    u64 gs = S & ((O << 1) | (u64)aIn) & ((O << 2) | (u64)cIn);
                    u32 gb = __ballot_sync(FULLM, gs != 0ull);
                    if (gb) {
                        // gs monotone; F pure function of gs -> iterate on gs
                        for (int it = 0; it < 256; it++) {
                            // 224-bit add P+gs via carry-lookahead across 4 lanes
                            u64 s = P + gs;
                            u32 gm = __ballot_sync(FULLM, s < P);        // generate
                            u32 pm = __ballot_sync(FULLM, s == ~0ull);   // propagate
                            u32 sh = lane & 28;
                            u32 gm4 = (gm >> sh) & 0xFu, pm4 = (pm >> sh) & 0xFu;
                            u32 c1 = gm4 & 1u;
                            u32 c2 = ((gm4 >> 1) & 1u) | (((pm4 >> 1) & 1u) & c1);
                            u32 c3 = ((gm4 >> 2) & 1u) | (((pm4 >> 2) & 1u) & c2);
                            u32 cw = (c1 << 1) | (c2 << 2) | (c3 << 3);
                            u64 s2 = s + (u64)((cw >> j) & 1u);
                            F = P & ~s2;                 // filled runs
                            u64 k = O | F;
                            u32 kh  = (u32)(k >> 62) & 3u;   // [1]=k63 [0]=k62
                            u32 khp = __shfl_up_sync(FULLM, kh, 1);
                            u32 aI = (j == 0) ? 1u : ((khp >> 1) & 1u);
                            u32 cI = (j == 0) ? 2u : (khp & 3u);
                            u64 gn = S & ((k << 1) | (u64)aI) & ((k << 2) | (u64)cI);
                            u32 chb = __ballot_sync(FULLM, gn != gs);
                            gs = gn;
                            if (!chb) break;
                        }
                    }
                }
                u64 nn = O | F;
                if (lane < 4) s_n[r][j] = nn;
                if (lane == 0) s_src[r] = r;
                r0 = r;
                u32 deb = __ballot_sync(FULLM, (nn ^ p1) != 0ull);
                e2 = e1; e1 = (deb == 0u);
                u32 nzb = __ballot_sync(FULLM, nn != 0ull);
                p1z = (nzb == 0u);
                if (nzb) {
                    if (hmin < 0) hmin = r;
                    hmax = r;
                    cm |= nn;
                    nzflag = 1;
                } else {
                    nzflag = 0;
                }
                p2 = p1; p1 = nn;
                r++;
            }
            // ---- finalize bbox + rect (within warp 0) ----
            if (lane < 4) s_cmA[j] = cm;
            __syncwarp();
            if (lane == 0) {
                u64 cm0 = s_cmA[0], cm1 = s_cmA[1], cm2 = s_cmA[2], cm3 = s_cmA[3];
                int wmin, wmax;
                if (hmin < 0) {   // empty: argmax-of-all-False semantics
                    hmin = 0; hmax = HH - 1; wmin = 0; wmax = WW - 1;
                } else {
                    if (cm0)      wmin = __ffsll((long long)cm0) - 1;
                    else if (cm1) wmin = 64  + __ffsll((long long)cm1) - 1;
                    else if (cm2) wmin = 128 + __ffsll((long long)cm2) - 1;
                    else          wmin = 192 + __ffsll((long long)cm3) - 1;
                    if (cm3)      wmax = 255 - __clzll((long long)cm3);
                    else if (cm2) wmax = 191 - __clzll((long long)cm2);
                    else if (cm1) wmax = 127 - __clzll((long long)cm1);
                    else          wmax = 63  - __clzll((long long)cm0);
                }
                // rect columns [wmin, wmax)  (wmax EXCLUSIVE, matching reference)
#pragma unroll
                for (int jj = 0; jj < 4; jj++)
                    s_rect[jj] = mask_lt(wmax, jj) & ~mask_lt(wmin, jj);
                s_hmin = hmin; s_hmax = hmax;
            }
        }
        __syncthreads();

        // ---- fused parallel phase: rect + diff + next b1/b2 + next flag bitmaps ----
        {
            const int hmin = s_hmin, hmax = s_hmax;
            const u64 rc0 = s_rect[0], rc1 = s_rect[1], rc2 = s_rect[2], rc3 = s_rect[3];
            u64 diff = 0;

#define PHASEB_ROW(RR, FLOUT) do {                                             \
        const int r_ = (RR);                                                   \
        const int sr_ = s_src[r_];                                             \
        bool in_ = (r_ >= hmin) && (r_ <= hmax);                               \
        u64 g0 = s_n[sr_][0] | (in_ ? rc0 : 0ull);                             \
        u64 g1 = s_n[sr_][1] | (in_ ? rc1 : 0ull);                             \
        u64 g2 = s_n[sr_][2] | (in_ ? rc2 : 0ull);                             \
        u64 g3 = s_n[sr_][3] | (in_ ? rc3 : 0ull);                             \
        diff |= (g0 ^ s_mask[r_][0]) | (g1 ^ s_mask[r_][1])                    \
              | (g2 ^ s_mask[r_][2]) | (g3 ^ s_mask[r_][3]);                   \
        s_mask[r_][0] = g0; s_mask[r_][1] = g1;                                \
        s_mask[r_][2] = g2; s_mask[r_][3] = g3;                                \
        u64 n0, n1, n2, n3;                                                    \
        if (r_ < HH - 2) {                                                     \
            const int sn_ = s_src[r_ + 1];                                     \
            bool in1_ = (r_ + 1 >= hmin) && (r_ + 1 <= hmax);                  \
            n0 = s_n[sn_][0] | (in1_ ? rc0 : 0ull);                            \
            n1 = s_n[sn_][1] | (in1_ ? rc1 : 0ull);                            \
            n2 = s_n[sn_][2] | (in1_ ? rc2 : 0ull);                            \
            n3 = s_n[sn_][3] | (in1_ ? rc3 : 0ull);                            \
        } else if (r_ == HH - 2) {                                             \
            n0 = ~0ull; n1 = ~0ull; n2 = ~0ull; n3 = W3MASK;                   \
        } else { n0 = n1 = n2 = n3 = 0ull; }                                   \
        u64 bl0 = g0 & n0, bl1 = g1 & n1, bl2 = g2 & n2, bl3 = g3 & n3;        \
        u64 rt0 = ((g0 >> 1) | (g1 << 63)) & g0;                               \
        u64 rt1 = ((g1 >> 1) | (g2 << 63)) & g1;                               \
        u64 rt2 = ((g2 >> 1) | (g3 << 63)) & g2;                               \
        u64 rt3 = ((g3 >> 1) | (1ull << 30)) & g3;                             \
        s_b1[r_][0] = bl0 ^ rt0; s_b1[r_][1] = bl1 ^ rt1;                      \
        s_b1[r_][2] = bl2 ^ rt2; s_b1[r_][3] = bl3 ^ rt3;                      \
        s_b2[r_][0] = bl0 & rt0; s_b2[r_][1] = bl1 & rt1;                      \
        s_b2[r_][2] = bl2 & rt2; s_b2[r_][3] = bl3 & rt3;                      \
        int fl_ = (((bl0 | rt0) | (bl1 | rt1) | (bl2 | rt2) | (bl3 | rt3))     \
                   == 0ull) ? 2 : 0;                                           \
        if (r_ >= 1 && r_ <= HH - 3) {                                         \
            const int sm_ = s_src[r_ - 1];                                     \
            bool inm_ = (r_ - 1 >= hmin) && (r_ - 1 <= hmax);                  \
            u64 m0 = s_n[sm_][0] | (inm_ ? rc0 : 0ull);                        \
            u64 m1 = s_n[sm_][1] | (inm_ ? rc1 : 0ull);                        \
            u64 m2 = s_n[sm_][2] | (inm_ ? rc2 : 0ull);                        \
            u64 m3 = s_n[sm_][3] | (inm_ ? rc3 : 0ull);                        \
            u64 d = (m0 ^ g0) | (m1 ^ g1) | (m2 ^ g2) | (m3 ^ g3)              \
                  | (g0 ^ n0) | (g1 ^ n1) | (g2 ^ n2) | (g3 ^ n3);             \
            fl_ |= (d == 0ull) ? 1 : 0;                                        \
        }                                                                      \
        FLOUT = fl_;                                                           \
    } while (0)

            {
                int fl;
                PHASEB_ROW(tid, fl);
                u32 f1 = __ballot_sync(FULLM, fl & 1);
                u32 f2 = __ballot_sync(FULLM, fl & 2);
                if (lane == 0) { s_fmap[warp] = f1; s_zmap[warp] = f2; }
            }
            if (tid < 96) {
                int fl;
                PHASEB_ROW(128 + tid, fl);
                u32 f1 = __ballot_sync(FULLM, fl & 1);
                u32 f2 = __ballot_sync(FULLM, fl & 2);
                if (lane == 0) { s_fmap[4 + warp] = f1; s_zmap[4 + warp] = f2; }
            }
            if (diff) s_chg[pass] = 1;   // benign multi-writer race (all write 1)
#undef PHASEB_ROW
        }
        __syncthreads();

        // converged: pass(m)==m, all remaining passes are identity
        if (!s_chg[pass]) break;   // write-once flag: no reset, no race
    }

    // ---- unpack to float ----
    for (int r = warp; r < HH; r += 4) {
#pragma unroll
        for (int c = 0; c < 7; c++) {
            int w = c * 32 + lane;
            oi[r * WW + w] = (float)((s_mask[r][w >> 6] >> (w & 63)) & 1ull);
        }
    }
}

extern "C" void kernel_launch(void* const* d_in, const int* in_sizes, int n_in,
                              void* d_out, int out_size) {
    const float* x = (const float*)d_in[0];
    float* out = (float*)d_out;
    int nimg = in_sizes[0] / IMG;   // B*C = 8
    mask_ca_kernel<<<nimg, 128>>>(x, out);
}

// round 12
// speedup vs baseline: 1.2212x; 1.0081x over previous
#include <cuda_runtime.h>

typedef unsigned long long u64;
typedef unsigned int u32;

#define HH 224
#define WW 224
#define IMG (HH * WW)
#define NPASS 9
#define W3MASK 0xFFFFFFFFull
#define FULLM 0xFFFFFFFFu

// bits 0..k-1 of word j (j*64 .. j*64+63) of a 224-bit mask
__device__ __forceinline__ u64 mask_lt(int k, int j) {
    int lo = j * 64;
    if (k <= lo) return 0ull;
    if (k >= lo + 64) return ~0ull;
    return (1ull << (k - lo)) - 1ull;
}

__global__ __launch_bounds__(128) void mask_ca_kernel(const float* __restrict__ x,
                                                      float* __restrict__ out) {
    __shared__ u64 s_mask[HH][4];   // current mask (post rect-fill)
    __shared__ u64 s_b1[HH][4];     // base == exactly one of below/right
    __shared__ u64 s_b2[HH][4];     // base == both
    __shared__ u64 s_n[HH][4];      // serial-scan output (pre rect-fill), sparse via s_src
    __shared__ int s_src[HH];       // representative row: value of row r is s_n[s_src[r]]
    __shared__ u32 s_fmap[8];       // bit r: g(r-1)==g(r)==g(r+1) (=> b(r)==b(r-1))
    __shared__ u32 s_zmap[8];       // bit r: (b1|b2)==0 at row r
    __shared__ u64 s_cmA[4];        // column-OR handoff, serial warp internal
    __shared__ u64 s_rect[4];
    __shared__ int s_hmin, s_hmax;
    __shared__ int s_chg[NPASS];    // write-once per pass (no reset race)

    const int tid  = threadIdx.x;
    const int lane = tid & 31;
    const int warp = tid >> 5;
    const float* xi = x + (size_t)blockIdx.x * IMG;
    float* oi = out + (size_t)blockIdx.x * IMG;

    // ---- pack input: threshold > 0.8, byte-wise, no ballots, deep MLP ----
    // byte b of row r covers cols 8b..8b+7 (little-endian matches u64 view).
    // bytes 28..31 of each 32-byte row are zeroed (bits 224..255 unused).
    {
        unsigned char* sb = (unsigned char*)s_mask;
#pragma unroll 4
        for (int idx = tid; idx < HH * 32; idx += 128) {
            int r = idx >> 5, b = idx & 31;
            unsigned char v = 0;
            if (b < 28) {
                const float4* p = (const float4*)(xi + r * WW + b * 8);
                float4 a = p[0], c = p[1];
                v = (unsigned char)((a.x > 0.8f)
                  | ((a.y > 0.8f) << 1)
                  | ((a.z > 0.8f) << 2)
                  | ((a.w > 0.8f) << 3)
                  | ((c.x > 0.8f) << 4)
                  | ((c.y > 0.8f) << 5)
                  | ((c.z > 0.8f) << 6)
                  | ((c.w > 0.8f) << 7));
            }
            sb[idx] = v;
        }
    }
    if (tid == 0) {
#pragma unroll
        for (int p = 0; p < NPASS; p++) s_chg[p] = 0;
    }
    __syncthreads();

    // ---- initial b1/b2 + flag bitmaps from packed input ----
#define INIT_ROW(RR, FLOUT) do {                                               \
        const int r_ = (RR);                                                   \
        u64 g0 = s_mask[r_][0], g1 = s_mask[r_][1];                            \
        u64 g2 = s_mask[r_][2], g3 = s_mask[r_][3];                            \
        u64 n0, n1, n2, n3;                                                    \
        if (r_ < HH - 2) {                                                     \
            n0 = s_mask[r_ + 1][0]; n1 = s_mask[r_ + 1][1];                    \
            n2 = s_mask[r_ + 1][2]; n3 = s_mask[r_ + 1][3];                    \
        } else if (r_ == HH - 2) {                                             \
            n0 = ~0ull; n1 = ~0ull; n2 = ~0ull; n3 = W3MASK;                   \
        } else { n0 = n1 = n2 = n3 = 0ull; }                                   \
        u64 bl0 = g0 & n0, bl1 = g1 & n1, bl2 = g2 & n2, bl3 = g3 & n3;        \
        u64 rt0 = ((g0 >> 1) | (g1 << 63)) & g0;                               \
        u64 rt1 = ((g1 >> 1) | (g2 << 63)) & g1;                               \
        u64 rt2 = ((g2 >> 1) | (g3 << 63)) & g2;                               \
        u64 rt3 = ((g3 >> 1) | (1ull << 30)) & g3;                             \
        s_b1[r_][0] = bl0 ^ rt0; s_b1[r_][1] = bl1 ^ rt1;                      \
        s_b1[r_][2] = bl2 ^ rt2; s_b1[r_][3] = bl3 ^ rt3;                      \
        s_b2[r_][0] = bl0 & rt0; s_b2[r_][1] = bl1 & rt1;                      \
        s_b2[r_][2] = bl2 & rt2; s_b2[r_][3] = bl3 & rt3;                      \
        int fl_ = (((bl0 | rt0) | (bl1 | rt1) | (bl2 | rt2) | (bl3 | rt3))     \
                   == 0ull) ? 2 : 0;                                           \
        if (r_ >= 1 && r_ <= HH - 3) {                                         \
            u64 m0 = s_mask[r_ - 1][0], m1 = s_mask[r_ - 1][1];                \
            u64 m2 = s_mask[r_ - 1][2], m3 = s_mask[r_ - 1][3];                \
            u64 d = (m0 ^ g0) | (m1 ^ g1) | (m2 ^ g2) | (m3 ^ g3)              \
                  | (g0 ^ n0) | (g1 ^ n1) | (g2 ^ n2) | (g3 ^ n3);             \
            fl_ |= (d == 0ull) ? 1 : 0;                                        \
        }                                                                      \
        FLOUT = fl_;                                                           \
    } while (0)

    {
        int fl;
        INIT_ROW(tid, fl);
        u32 f1 = __ballot_sync(FULLM, fl & 1);
        u32 f2 = __ballot_sync(FULLM, fl & 2);
        if (lane == 0) { s_fmap[warp] = f1; s_zmap[warp] = f2; }
    }
    if (tid < 96) {
        int fl;
        INIT_ROW(128 + tid, fl);
        u32 f1 = __ballot_sync(FULLM, fl & 1);
        u32 f2 = __ballot_sync(FULLM, fl & 2);
        if (lane == 0) { s_fmap[4 + warp] = f1; s_zmap[4 + warp] = f2; }
    }
    __syncthreads();

    for (int pass = 0; pass < NPASS; pass++) {
        // ---- serial raster recurrence, warp-SIMD: word j=lane&3 per lane ----
        // 8 replicated lane-groups => all branches warp-uniform; split-predicate
        // ballots carry two scalars per vote (nibble 0 = group 0, nibble 4 = group 4).
        if (warp == 0) {
            const int j = lane & 3;
            const bool loTest = (lane < 16);
            u32 fm[7], zm[7];
#pragma unroll
            for (int jj = 0; jj < 7; jj++) { fm[jj] = s_fmap[jj]; zm[jj] = s_zmap[jj]; }
            u64 p1 = (j < 3) ? ~0ull : W3MASK;   // virtual row -1 = ones
            u64 p2 = 0ull;                        // virtual row -2 = zeros
            u64 cm = 0ull;
            int hmin = -1, hmax = -1;
            int e1 = 0, e2 = 0, p1z = 0, nzflag = 0, r0 = 0;
            int r = 0;
            while (r < HH) {
                const int w = r >> 5, bpos = r & 31;
                if ((e1 & e2) && ((fm[w] >> bpos) & 1)) {
                    // hit RUN: consecutive rows with b(q)==b(q-1); nn stays == p1
                    int end;
                    u32 xbits = (~fm[w]) >> bpos;
                    if (xbits) end = r + __ffs(xbits) - 1;
                    else {
                        int ww = w + 1;
                        while (ww < 7 && fm[ww] == FULLM) ww++;
                        end = (ww < 7) ? ww * 32 + __ffs(~fm[ww]) - 1 : HH;
                    }
                    if (end > HH) end = HH;
                    for (int q = r + lane; q < end; q += 32) s_src[q] = r0;
                    if (nzflag) hmax = end - 1;
                    r = end;
                    continue;
                }
                if ((zm[w] >> bpos) & 1) {
                    // zero row: b1|b2==0 -> nn=0 for ANY ab (O=0 keeps seed empty)
                    if (lane < 4) s_n[r][j] = 0ull;
                    if (lane == 0) s_src[r] = r;
                    r0 = r;
                    e2 = e1; e1 = p1z; p1z = 1; nzflag = 0;
                    p2 = p1; p1 = 0ull;
                    r++;
                    continue;
                }
                // ---- miss: full row, one 64-bit word per lane ----
                u64 ab = p1 & p2;
                u64 b1 = s_b1[r][j], b2 = s_b2[r][j];
                u64 O = b2 | (b1 & ab);      // a>=2
                u64 P = (b1 ^ ab) & ~b2;     // a==1
                u64 F = 0ull;
                // seed computed unconditionally (saves the P!=0 guard ballot)
                // cross-word bits from lane j-1: [2]=P63, [1]=O63, [0]=O62
                u32 hi = ((u32)(P >> 63) << 2) | ((u32)(O >> 62) & 3u);
                u32 hp = __shfl_up_sync(FULLM, hi, 1);
                u32 sIn = (j == 0) ? 0u : ((hp >> 2) & 1u);
                u32 aIn = (j == 0) ? 1u : ((hp >> 1) & 1u);   // virtual n(-1)=1
                u32 cIn = (j == 0) ? 2u : (hp & 3u);          // virtual n(-2)=0
                u64 S  = P & ~((P << 1) | (u64)sIn);          // run starts
                u64 gs = S & ((O << 1) | (u64)aIn) & ((O << 2) | (u64)cIn);
                u32 gb = __ballot_sync(FULLM, gs != 0ull);
                if (gb) {
                    // gs monotone; F pure function of gs -> iterate on gs
                    for (int it = 0; it < 256; it++) {
                        // 224-bit add P+gs; generate/propagate share one ballot
                        u64 s = P + gs;
                        u32 bal2 = __ballot_sync(FULLM,
                                       loTest ? (s < P) : (s == ~0ull));
                        u32 gm4 = bal2 & 0xFu;           // generate, words 0..3
                        u32 pm4 = (bal2 >> 16) & 0xFu;   // propagate, words 0..3
                        u32 c1 = gm4 & 1u;
                        u32 c2 = ((gm4 >> 1) & 1u) | (((pm4 >> 1) & 1u) & c1);
                        u32 c3 = ((gm4 >> 2) & 1u) | (((pm4 >> 2) & 1u) & c2);
                        u32 cw = (c1 << 1) | (c2 << 2) | (c3 << 3);
                        u64 s2 = s + (u64)((cw >> j) & 1u);
                        F = P & ~s2;                 // filled runs
                        u64 k = O | F;
                        u32 kh  = (u32)(k >> 62) & 3u;   // [1]=k63 [0]=k62
                        u32 khp = __shfl_up_sync(FULLM, kh, 1);
                        u32 aI = (j == 0) ? 1u : ((khp >> 1) & 1u);
                        u32 cI = (j == 0) ? 2u : (khp & 3u);
                        u64 gn = S & ((k << 1) | (u64)aI) & ((k << 2) | (u64)cI);
                        u32 chb = __ballot_sync(FULLM, gn != gs);
                        gs = gn;
                        if (!chb) break;
                    }
                }
                u64 nn = O | F;
                if (lane < 4) s_n[r][j] = nn;
                if (lane == 0) s_src[r] = r;
                r0 = r;
                // merged ballot: nibble0 = nn!=p1 per word, nibble4 = nn!=0 per word
                u32 bal = __ballot_sync(FULLM,
                              loTest ? ((nn ^ p1) != 0ull) : (nn != 0ull));
                e2 = e1; e1 = ((bal & 0xFu) == 0u);
                int nz = (((bal >> 16) & 0xFu) != 0u);
                p1z = !nz;
                if (nz) {
                    if (hmin < 0) hmin = r;
                    hmax = r;
                    cm |= nn;
                    nzflag = 1;
                } else {
                    nzflag = 0;
                }
                p2 = p1; p1 = nn;
                r++;
            }
            // ---- finalize bbox + rect (within warp 0) ----
            if (lane < 4) s_cmA[j] = cm;
            __syncwarp();
            if (lane == 0) {
                u64 cm0 = s_cmA[0], cm1 = s_cmA[1], cm2 = s_cmA[2], cm3 = s_cmA[3];
                int wmin, wmax;
                if (hmin < 0) {   // empty: argmax-of-all-False semantics
                    hmin = 0; hmax = HH - 1; wmin = 0; wmax = WW - 1;
                } else {
                    if (cm0)      wmin = __ffsll((long long)cm0) - 1;
                    else if (cm1) wmin = 64  + __ffsll((long long)cm1) - 1;
                    else if (cm2) wmin = 128 + __ffsll((long long)cm2) - 1;
                    else          wmin = 192 + __ffsll((long long)cm3) - 1;
                    if (cm3)      wmax = 255 - __clzll((long long)cm3);
                    else if (cm2) wmax = 191 - __clzll((long long)cm2);
                    else if (cm1) wmax = 127 - __clzll((long long)cm1);
                    else          wmax = 63  - __clzll((long long)cm0);
                }
                // rect columns [wmin, wmax)  (wmax EXCLUSIVE, matching reference)
#pragma unroll
                for (int jj = 0; jj < 4; jj++)
                    s_rect[jj] = mask_lt(wmax, jj) & ~mask_lt(wmin, jj);
                s_hmin = hmin; s_hmax = hmax;
            }
        }
        __syncthreads();

        // ---- fused parallel phase: rect + diff + next b1/b2 + next flag bitmaps ----
        {
            const int hmin = s_hmin, hmax = s_hmax;
            const u64 rc0 = s_rect[0], rc1 = s_rect[1], rc2 = s_rect[2], rc3 = s_rect[3];
            u64 diff = 0;

#define PHASEB_ROW(RR, FLOUT) do {                                             \
        const int r_ = (RR);                                                   \
        const int sr_ = s_src[r_];                                             \
        bool in_ = (r_ >= hmin) && (r_ <= hmax);                               \
        u64 g0 = s_n[sr_][0] | (in_ ? rc0 : 0ull);                             \
        u64 g1 = s_n[sr_][1] | (in_ ? rc1 : 0ull);                             \
        u64 g2 = s_n[sr_][2] | (in_ ? rc2 : 0ull);                             \
        u64 g3 = s_n[sr_][3] | (in_ ? rc3 : 0ull);                             \
        diff |= (g0 ^ s_mask[r_][0]) | (g1 ^ s_mask[r_][1])                    \
              | (g2 ^ s_mask[r_][2]) | (g3 ^ s_mask[r_][3]);                   \
        s_mask[r_][0] = g0; s_mask[r_][1] = g1;                                \
        s_mask[r_][2] = g2; s_mask[r_][3] = g3;                                \
        u64 n0, n1, n2, n3;                                                    \
        if (r_ < HH - 2) {                                                     \
            const int sn_ = s_src[r_ + 1];                                     \
            bool in1_ = (r_ + 1 >= hmin) && (r_ + 1 <= hmax);                  \
            n0 = s_n[sn_][0] | (in1_ ? rc0 : 0ull);                            \
            n1 = s_n[sn_][1] | (in1_ ? rc1 : 0ull);                            \
            n2 = s_n[sn_][2] | (in1_ ? rc2 : 0ull);                            \
            n3 = s_n[sn_][3] | (in1_ ? rc3 : 0ull);                            \
        } else if (r_ == HH - 2) {                                             \
            n0 = ~0ull; n1 = ~0ull; n2 = ~0ull; n3 = W3MASK;                   \
        } else { n0 = n1 = n2 = n3 = 0ull; }                                   \
        u64 bl0 = g0 & n0, bl1 = g1 & n1, bl2 = g2 & n2, bl3 = g3 & n3;        \
        u64 rt0 = ((g0 >> 1) | (g1 << 63)) & g0;                               \
        u64 rt1 = ((g1 >> 1) | (g2 << 63)) & g1;                               \
        u64 rt2 = ((g2 >> 1) | (g3 << 63)) & g2;                               \
        u64 rt3 = ((g3 >> 1) | (1ull << 30)) & g3;                             \
        s_b1[r_][0] = bl0 ^ rt0; s_b1[r_][1] = bl1 ^ rt1;                      \
        s_b1[r_][2] = bl2 ^ rt2; s_b1[r_][3] = bl3 ^ rt3;                      \
        s_b2[r_][0] = bl0 & rt0; s_b2[r_][1] = bl1 & rt1;                      \
        s_b2[r_][2] = bl2 & rt2; s_b2[r_][3] = bl3 & rt3;                      \
        int fl_ = (((bl0 | rt0) | (bl1 | rt1) | (bl2 | rt2) | (bl3 | rt3))     \
                   == 0ull) ? 2 : 0;                                           \
        if (r_ >= 1 && r_ <= HH - 3) {                                         \
            const int sm_ = s_src[r_ - 1];                                     \
            bool inm_ = (r_ - 1 >= hmin) && (r_ - 1 <= hmax);                  \
            u64 m0 = s_n[sm_][0] | (inm_ ? rc0 : 0ull);                        \
            u64 m1 = s_n[sm_][1] | (inm_ ? rc1 : 0ull);                        \
            u64 m2 = s_n[sm_][2] | (inm_ ? rc2 : 0ull);                        \
            u64 m3 = s_n[sm_][3] | (inm_ ? rc3 : 0ull);                        \
            u64 d = (m0 ^ g0) | (m1 ^ g1) | (m2 ^ g2) | (m3 ^ g3)              \
                  | (g0 ^ n0) | (g1 ^ n1) | (g2 ^ n2) | (g3 ^ n3);             \
            fl_ |= (d == 0ull) ? 1 : 0;                                        \
        }                                                                      \
        FLOUT = fl_;                                                           \
    } while (0)

            {
                int fl;
                PHASEB_ROW(tid, fl);
                u32 f1 = __ballot_sync(FULLM, fl & 1);
                u32 f2 = __ballot_sync(FULLM, fl & 2);
                if (lane == 0) { s_fmap[warp] = f1; s_zmap[warp] = f2; }
            }
            if (tid < 96) {
                int fl;
                PHASEB_ROW(128 + tid, fl);
                u32 f1 = __ballot_sync(FULLM, fl & 1);
                u32 f2 = __ballot_sync(FULLM, fl & 2);
                if (lane == 0) { s_fmap[4 + warp] = f1; s_zmap[4 + warp] = f2; }
            }
            if (diff) s_chg[pass] = 1;   // benign multi-writer race (all write 1)
#undef PHASEB_ROW
        }
        __syncthreads();

        // converged: pass(m)==m, all remaining passes are identity
        if (!s_chg[pass]) break;   // write-once flag: no reset, no race
    }

    // ---- unpack to float: one float4 per 4 columns ----
#pragma unroll 4
    for (int idx = tid; idx < IMG / 4; idx += 128) {
        int r = idx / 56, cg = idx - r * 56;
        int col = cg * 4;                       // 4-aligned: nibble within one word
        u32 bits = (u32)(s_mask[r][col >> 6] >> (col & 63)) & 0xFu;
        float4 o;
        o.x = (bits & 1u) ? 1.0f : 0.0f;
        o.y = (bits & 2u) ? 1.0f : 0.0f;
        o.z = (bits & 4u) ? 1.0f : 0.0f;
        o.w = (bits & 8u) ? 1.0f : 0.0f;
        ((float4*)oi)[idx] = o;
    }
}

extern "C" void kernel_launch(void* const* d_in, const int* in_sizes, int n_in,
                              void* d_out, int out_size) {
    const float* x = (const float*)d_in[0];
    float* out = (float*)d_out;
    int nimg = in_sizes[0] / IMG;   // B*C = 8
    mask_ca_kernel<<<nimg, 128>>>(x, out);
}

// round 13
// speedup vs baseline: 1.6090x; 1.3175x over previous
#include <cuda_runtime.h>

typedef unsigned long long u64;
typedef unsigned int u32;

#define HH 224
#define WW 224
#define IMG (HH * WW)
#define NPASS 9
#define W3MASK 0xFFFFFFFFull
#define FULLM 0xFFFFFFFFu

// bits 0..k-1 of word j (j*64 .. j*64+63) of a 224-bit mask
__device__ __forceinline__ u64 mask_lt(int k, int j) {
    int lo = j * 64;
    if (k <= lo) return 0ull;
    if (k >= lo + 64) return ~0ull;
    return (1ull << (k - lo)) - 1ull;
}

// first row e >= q such that row e-1 is a zero-b row (z-bit set); HH if none.
// q >= 1. Segment starting at e may be initialized with (p1,p2)=(0,0): exact.
__device__ __forceinline__ int find_entry(const u32* zm, int q) {
    int pos = q - 1;
    int w = pos >> 5;
    u32 bits = zm[w] & (FULLM << (pos & 31));
    while (bits == 0) {
        if (++w >= 7) return HH;
        bits = zm[w];
    }
    int z = (w << 5) + __ffs(bits) - 1;
    return (z + 1 > HH) ? HH : z + 1;
}

__global__ __launch_bounds__(128) void mask_ca_kernel(const float* __restrict__ x,
                                                      float* __restrict__ out) {
    __shared__ u64 s_mask[HH][4];   // current mask (post rect-fill)
    __shared__ u64 s_b1[HH][4];     // base == exactly one of below/right
    __shared__ u64 s_b2[HH][4];     // base == both
    __shared__ u64 s_n[HH][4];      // serial-scan output (pre rect-fill), sparse via s_src
    __shared__ int s_src[HH];       // representative row: value of row r is s_n[s_src[r]]
    __shared__ u32 s_fmap[8];       // bit r: g(r-1)==g(r)==g(r+1) (=> b(r)==b(r-1))
    __shared__ u32 s_zmap[8];       // bit r: (b1|b2)==0 at row r (carry barrier!)
    __shared__ u64 s_wcm[4][4];     // per-warp column-OR of its rows
    __shared__ int s_whmin[4], s_whmax[4];
    __shared__ int s_chg[NPASS];    // write-once per pass (no reset race)

    const int tid  = threadIdx.x;
    const int lane = tid & 31;
    const int warp = tid >> 5;
    const float* xi = x + (size_t)blockIdx.x * IMG;
    float* oi = out + (size_t)blockIdx.x * IMG;

    // ---- pack input: threshold > 0.8, byte-wise, no ballots, deep MLP ----
    {
        unsigned char* sb = (unsigned char*)s_mask;
#pragma unroll 4
        for (int idx = tid; idx < HH * 32; idx += 128) {
            int r = idx >> 5, b = idx & 31;
            unsigned char v = 0;
            if (b < 28) {
                const float4* p = (const float4*)(xi + r * WW + b * 8);
                float4 a = p[0], c = p[1];
                v = (unsigned char)((a.x > 0.8f)
                  | ((a.y > 0.8f) << 1)
                  | ((a.z > 0.8f) << 2)
                  | ((a.w > 0.8f) << 3)
                  | ((c.x > 0.8f) << 4)
                  | ((c.y > 0.8f) << 5)
                  | ((c.z > 0.8f) << 6)
                  | ((c.w > 0.8f) << 7));
            }
            sb[idx] = v;
        }
    }
    if (tid == 0) {
#pragma unroll
        for (int p = 0; p < NPASS; p++) s_chg[p] = 0;
    }
    __syncthreads();

    // ---- initial b1/b2 + flag bitmaps from packed input ----
#define INIT_ROW(RR, FLOUT) do {                                               \
        const int r_ = (RR);                                                   \
        u64 g0 = s_mask[r_][0], g1 = s_mask[r_][1];                            \
        u64 g2 = s_mask[r_][2], g3 = s_mask[r_][3];                            \
        u64 n0, n1, n2, n3;                                                    \
        if (r_ < HH - 2) {                                                     \
            n0 = s_mask[r_ + 1][0]; n1 = s_mask[r_ + 1][1];                    \
            n2 = s_mask[r_ + 1][2]; n3 = s_mask[r_ + 1][3];                    \
        } else if (r_ == HH - 2) {                                             \
            n0 = ~0ull; n1 = ~0ull; n2 = ~0ull; n3 = W3MASK;                   \
        } else { n0 = n1 = n2 = n3 = 0ull; }                                   \
        u64 bl0 = g0 & n0, bl1 = g1 & n1, bl2 = g2 & n2, bl3 = g3 & n3;        \
        u64 rt0 = ((g0 >> 1) | (g1 << 63)) & g0;                               \
        u64 rt1 = ((g1 >> 1) | (g2 << 63)) & g1;                               \
        u64 rt2 = ((g2 >> 1) | (g3 << 63)) & g2;                               \
        u64 rt3 = ((g3 >> 1) | (1ull << 30)) & g3;                             \
        s_b1[r_][0] = bl0 ^ rt0; s_b1[r_][1] = bl1 ^ rt1;                      \
        s_b1[r_][2] = bl2 ^ rt2; s_b1[r_][3] = bl3 ^ rt3;                      \
        s_b2[r_][0] = bl0 & rt0; s_b2[r_][1] = bl1 & rt1;                      \
        s_b2[r_][2] = bl2 & rt2; s_b2[r_][3] = bl3 & rt3;                      \
        int fl_ = (((bl0 | rt0) | (bl1 | rt1) | (bl2 | rt2) | (bl3 | rt3))     \
                   == 0ull) ? 2 : 0;                                           \
        if (r_ >= 1 && r_ <= HH - 3) {                                         \
            u64 m0 = s_mask[r_ - 1][0], m1 = s_mask[r_ - 1][1];                \
            u64 m2 = s_mask[r_ - 1][2], m3 = s_mask[r_ - 1][3];                \
            u64 d = (m0 ^ g0) | (m1 ^ g1) | (m2 ^ g2) | (m3 ^ g3)              \
                  | (g0 ^ n0) | (g1 ^ n1) | (g2 ^ n2) | (g3 ^ n3);             \
            fl_ |= (d == 0ull) ? 1 : 0;                                        \
        }                                                                      \
        FLOUT = fl_;                                                           \
    } while (0)

    {
        int fl;
        INIT_ROW(tid, fl);
        u32 f1 = __ballot_sync(FULLM, fl & 1);
        u32 f2 = __ballot_sync(FULLM, fl & 2);
        if (lane == 0) { s_fmap[warp] = f1; s_zmap[warp] = f2; }
    }
    if (tid < 96) {
        int fl;
        INIT_ROW(128 + tid, fl);
        u32 f1 = __ballot_sync(FULLM, fl & 1);
        u32 f2 = __ballot_sync(FULLM, fl & 2);
        if (lane == 0) { s_fmap[4 + warp] = f1; s_zmap[4 + warp] = f2; }
    }
    __syncthreads();

    for (int pass = 0; pass < NPASS; pass++) {
        // ---- serial raster recurrence, 4 warps on disjoint segments ----
        // Carry-barrier lemma: a zero-b row q forces nn(q)=0 and ab==0 for the
        // next two rows, so a scan started at q+1 with (p1,p2)=(0,0) is exact.
        // Warp k owns rows [entry_k, entry_{k+1}), entry_k = first row >= 56k
        // preceded by a zero-b row (entry_0 = 0 with the virtual carry).
        {
            const int j = lane & 3;
            const bool loTest = (lane < 16);
            u32 fm[7], zm[7];
#pragma unroll
            for (int jj = 0; jj < 7; jj++) { fm[jj] = s_fmap[jj]; zm[jj] = s_zmap[jj]; }
            const int entry = (warp == 0) ? 0 : find_entry(zm, 56 * warp);
            const int end   = (warp == 3) ? HH : find_entry(zm, 56 * (warp + 1));

            u64 p1 = 0ull, p2 = 0ull;
            if (warp == 0) p1 = (j < 3) ? ~0ull : W3MASK;   // virtual row -1 = ones
            u64 cm = 0ull;
            int hmin = 1 << 30, hmax = -1;
            int e1 = 0, e2 = 0, p1z = 0, nzflag = 0, r0 = entry;
            int r = entry;
            while (r < end) {
                const int w = r >> 5, bpos = r & 31;
                if ((e1 & e2) && ((fm[w] >> bpos) & 1)) {
                    // hit RUN: consecutive rows with b(q)==b(q-1); nn stays == p1
                    int erun;
                    u32 xbits = (~fm[w]) >> bpos;
                    if (xbits) erun = r + __ffs(xbits) - 1;
                    else {
                        int ww = w + 1;
                        while (ww < 7 && fm[ww] == FULLM) ww++;
                        erun = (ww < 7) ? ww * 32 + __ffs(~fm[ww]) - 1 : HH;
                    }
                    if (erun > end) erun = end;
                    for (int q = r + lane; q < erun; q += 32) s_src[q] = r0;
                    if (nzflag) hmax = erun - 1;   // hmin/cm already reflect this value
                    r = erun;
                    continue;
                }
                if ((zm[w] >> bpos) & 1) {
                    // zero row: b1|b2==0 -> nn=0 for ANY ab (O=0 keeps seed empty)
                    if (lane < 4) s_n[r][j] = 0ull;
                    if (lane == 0) s_src[r] = r;
                    r0 = r;
                    e2 = e1; e1 = p1z; p1z = 1; nzflag = 0;
                    p2 = p1; p1 = 0ull;
                    r++;
                    continue;
                }
                // ---- miss: full row, one 64-bit word per lane ----
                u64 ab = p1 & p2;
                u64 b1 = s_b1[r][j], b2 = s_b2[r][j];
                u64 O = b2 | (b1 & ab);      // a>=2
                u64 P = (b1 ^ ab) & ~b2;     // a==1
                u64 F = 0ull;
                // cross-word bits from lane j-1: [2]=P63, [1]=O63, [0]=O62
                u32 hi = ((u32)(P >> 63) << 2) | ((u32)(O >> 62) & 3u);
                u32 hp = __shfl_up_sync(FULLM, hi, 1);
                u32 sIn = (j == 0) ? 0u : ((hp >> 2) & 1u);
                u32 aIn = (j == 0) ? 1u : ((hp >> 1) & 1u);   // virtual n(-1)=1
                u32 cIn = (j == 0) ? 2u : (hp & 3u);          // virtual n(-2)=0
                u64 S  = P & ~((P << 1) | (u64)sIn);          // run starts
                u64 gs = S & ((O << 1) | (u64)aIn) & ((O << 2) | (u64)cIn);
                u32 gb = __ballot_sync(FULLM, gs != 0ull);
                if (gb) {
                    // gs monotone; F pure function of gs -> iterate on gs
                    for (int it = 0; it < 256; it++) {
                        // 224-bit add P+gs; generate/propagate share one ballot
                        u64 s = P + gs;
                        u32 bal2 = __ballot_sync(FULLM,
                                       loTest ? (s < P) : (s == ~0ull));
                        u32 gm4 = bal2 & 0xFu;           // generate, words 0..3
                        u32 pm4 = (bal2 >> 16) & 0xFu;   // propagate, words 0..3
                        u32 c1 = gm4 & 1u;
                        u32 c2 = ((gm4 >> 1) & 1u) | (((pm4 >> 1) & 1u) & c1);
                        u32 c3 = ((gm4 >> 2) & 1u) | (((pm4 >> 2) & 1u) & c2);
                        u32 cw = (c1 << 1) | (c2 << 2) | (c3 << 3);
                        u64 s2 = s + (u64)((cw >> j) & 1u);
                        F = P & ~s2;                 // filled runs
                        u64 k = O | F;
                        u32 kh  = (u32)(k >> 62) & 3u;   // [1]=k63 [0]=k62
                        u32 khp = __shfl_up_sync(FULLM, kh, 1);
                        u32 aI = (j == 0) ? 1u : ((khp >> 1) & 1u);
                        u32 cI = (j == 0) ? 2u : (khp & 3u);
                        u64 gn = S & ((k << 1) | (u64)aI) & ((k << 2) | (u64)cI);
                        u32 chb = __ballot_sync(FULLM, gn != gs);
                        gs = gn;
                        if (!chb) break;
                    }
                }
                u64 nn = O | F;
                if (lane < 4) s_n[r][j] = nn;
                if (lane == 0) s_src[r] = r;
                r0 = r;
                // merged ballot: nibble0 = nn!=p1 per word, nibble4 = nn!=0 per word
                u32 bal = __ballot_sync(FULLM,
                              loTest ? ((nn ^ p1) != 0ull) : (nn != 0ull));
                e2 = e1; e1 = ((bal & 0xFu) == 0u);
                int nz = (((bal >> 16) & 0xFu) != 0u);
                p1z = !nz;
                if (nz) {
                    if (hmax < 0) hmin = r;
                    hmax = r;
                    cm |= nn;
                    nzflag = 1;
                } else {
                    nzflag = 0;
                }
                p2 = p1; p1 = nn;
                r++;
            }
            // per-warp bbox handoff (no atomics; fixed slots)
            if (lane < 4) s_wcm[warp][j] = cm;
            if (lane == 0) { s_whmin[warp] = hmin; s_whmax[warp] = hmax; }
        }
        __syncthreads();   // B1: s_n + per-warp bbox ready

        // ---- fused parallel phase: combine bbox + rect + diff + next b/flags ----
        {
            // every thread combines the 4 warp results (replicated, branch-free)
            int hmin = min(min(s_whmin[0], s_whmin[1]), min(s_whmin[2], s_whmin[3]));
            int hmax = max(max(s_whmax[0], s_whmax[1]), max(s_whmax[2], s_whmax[3]));
            u64 cm0 = s_wcm[0][0] | s_wcm[1][0] | s_wcm[2][0] | s_wcm[3][0];
            u64 cm1 = s_wcm[0][1] | s_wcm[1][1] | s_wcm[2][1] | s_wcm[3][1];
            u64 cm2 = s_wcm[0][2] | s_wcm[1][2] | s_wcm[2][2] | s_wcm[3][2];
            u64 cm3 = s_wcm[0][3] | s_wcm[1][3] | s_wcm[2][3] | s_wcm[3][3];
            int wmin, wmax;
            if (hmax < 0) {   // empty: argmax-of-all-False semantics
                hmin = 0; hmax = HH - 1; wmin = 0; wmax = WW - 1;
            } else {
                if (cm0)      wmin = __ffsll((long long)cm0) - 1;
                else if (cm1) wmin = 64  + __ffsll((long long)cm1) - 1;
                else if (cm2) wmin = 128 + __ffsll((long long)cm2) - 1;
                else          wmin = 192 + __ffsll((long long)cm3) - 1;
                if (cm3)      wmax = 255 - __clzll((long long)cm3);
                else if (cm2) wmax = 191 - __clzll((long long)cm2);
                else if (cm1) wmax = 127 - __clzll((long long)cm1);
                else          wmax = 63  - __clzll((long long)cm0);
            }
            // rect columns [wmin, wmax)  (wmax EXCLUSIVE, matching reference slice)
            const u64 rc0 = mask_lt(wmax, 0) & ~mask_lt(wmin, 0);
            const u64 rc1 = mask_lt(wmax, 1) & ~mask_lt(wmin, 1);
            const u64 rc2 = mask_lt(wmax, 2) & ~mask_lt(wmin, 2);
            const u64 rc3 = mask_lt(wmax, 3) & ~mask_lt(wmin, 3);
            u64 diff = 0;

#define PHASEB_ROW(RR, FLOUT) do {                                             \
        const int r_ = (RR);                                                   \
        const int sr_ = s_src[r_];                                             \
        bool in_ = (r_ >= hmin) && (r_ <= hmax);                               \
        u64 g0 = s_n[sr_][0] | (in_ ? rc0 : 0ull);                             \
        u64 g1 = s_n[sr_][1] | (in_ ? rc1 : 0ull);                             \
        u64 g2 = s_n[sr_][2] | (in_ ? rc2 : 0ull);                             \
        u64 g3 = s_n[sr_][3] | (in_ ? rc3 : 0ull);                             \
        diff |= (g0 ^ s_mask[r_][0]) | (g1 ^ s_mask[r_][1])                    \
              | (g2 ^ s_mask[r_][2]) | (g3 ^ s_mask[r_][3]);                   \
        s_mask[r_][0] = g0; s_mask[r_][1] = g1;                                \
        s_mask[r_][2] = g2; s_mask[r_][3] = g3;                                \
        u64 n0, n1, n2, n3;                                                    \
        if (r_ < HH - 2) {                                                     \
            const int sn_ = s_src[r_ + 1];                                     \
            bool in1_ = (r_ + 1 >= hmin) && (r_ + 1 <= hmax);                  \
            n0 = s_n[sn_][0] | (in1_ ? rc0 : 0ull);                            \
            n1 = s_n[sn_][1] | (in1_ ? rc1 : 0ull);                            \
            n2 = s_n[sn_][2] | (in1_ ? rc2 : 0ull);                            \
            n3 = s_n[sn_][3] | (in1_ ? rc3 : 0ull);                            \
        } else if (r_ == HH - 2) {                                             \
            n0 = ~0ull; n1 = ~0ull; n2 = ~0ull; n3 = W3MASK;                   \
        } else { n0 = n1 = n2 = n3 = 0ull; }                                   \
        u64 bl0 = g0 & n0, bl1 = g1 & n1, bl2 = g2 & n2, bl3 = g3 & n3;        \
        u64 rt0 = ((g0 >> 1) | (g1 << 63)) & g0;                               \
        u64 rt1 = ((g1 >> 1) | (g2 << 63)) & g1;                               \
        u64 rt2 = ((g2 >> 1) | (g3 << 63)) & g2;                               \
        u64 rt3 = ((g3 >> 1) | (1ull << 30)) & g3;                             \
        s_b1[r_][0] = bl0 ^ rt0; s_b1[r_][1] = bl1 ^ rt1;                      \
        s_b1[r_][2] = bl2 ^ rt2; s_b1[r_][3] = bl3 ^ rt3;                      \
        s_b2[r_][0] = bl0 & rt0; s_b2[r_][1] = bl1 & rt1;                      \
        s_b2[r_][2] = bl2 & rt2; s_b2[r_][3] = bl3 & rt3;                      \
        int fl_ = (((bl0 | rt0) | (bl1 | rt1) | (bl2 | rt2) | (bl3 | rt3))     \
                   == 0ull) ? 2 : 0;                                           \
        if (r_ >= 1 && r_ <= HH - 3) {                                         \
            const int sm_ = s_src[r_ - 1];                                     \
            bool inm_ = (r_ - 1 >= hmin) && (r_ - 1 <= hmax);                  \
            u64 m0 = s_n[sm_][0] | (inm_ ? rc0 : 0ull);                        \
            u64 m1 = s_n[sm_][1] | (inm_ ? rc1 : 0ull);                        \
            u64 m2 = s_n[sm_][2] | (inm_ ? rc2 : 0ull);                        \
            u64 m3 = s_n[sm_][3] | (inm_ ? rc3 : 0ull);                        \
            u64 d = (m0 ^ g0) | (m1 ^ g1) | (m2 ^ g2) | (m3 ^ g3)              \
                  | (g0 ^ n0) | (g1 ^ n1) | (g2 ^ n2) | (g3 ^ n3);             \
            fl_ |= (d == 0ull) ? 1 : 0;                                        \
        }                                                                      \
        FLOUT = fl_;                                                           \
    } while (0)

            {
                int fl;
                PHASEB_ROW(tid, fl);
                u32 f1 = __ballot_sync(FULLM, fl & 1);
                u32 f2 = __ballot_sync(FULLM, fl & 2);
                if (lane == 0) { s_fmap[warp] = f1; s_zmap[warp] = f2; }
            }
            if (tid < 96) {
                int fl;
                PHASEB_ROW(128 + tid, fl);
                u32 f1 = __ballot_sync(FULLM, fl & 1);
                u32 f2 = __ballot_sync(FULLM, fl & 2);
                if (lane == 0) { s_fmap[4 + warp] = f1; s_zmap[4 + warp] = f2; }
            }
            if (diff) s_chg[pass] = 1;   // benign multi-writer race (all write 1)
#undef PHASEB_ROW
        }
        __syncthreads();

        // converged: pass(m)==m, all remaining passes are identity
        if (!s_chg[pass]) break;   // write-once flag: no reset, no race
    }

    // ---- unpack to float: one float4 per 4 columns ----
#pragma unroll 4
    for (int idx = tid; idx < IMG / 4; idx += 128) {
        int r = idx / 56, cg = idx - r * 56;
        int col = cg * 4;                       // 4-aligned: nibble within one word
        u32 bits = (u32)(s_mask[r][col >> 6] >> (col & 63)) & 0xFu;
        float4 o;
        o.x = (bits & 1u) ? 1.0f : 0.0f;
        o.y = (bits & 2u) ? 1.0f : 0.0f;
        o.z = (bits & 4u) ? 1.0f : 0.0f;
        o.w = (bits & 8u) ? 1.0f : 0.0f;
        ((float4*)oi)[idx] = o;
    }
}

extern "C" void kernel_launch(void* const* d_in, const int* in_sizes, int n_in,
                              void* d_out, int out_size) {
    const float* x = (const float*)d_in[0];
    float* out = (float*)d_out;
    int nimg = in_sizes[0] / IMG;   // B*C = 8
    mask_ca_kernel<<<nimg, 128>>>(x, out);
}